// round 11
// baseline (speedup 1.0000x reference)
#include <cuda_runtime.h>
#include <cuda_bf16.h>
#include <math.h>

// Problem dims (fixed by the dataset)
#define BDIM 512      // batch (codes)
#define CDIM 256      // feature dim
#define HDIM 1024     // hidden dim
#define NCB  500000   // codebook rows
#define NTILE 32      // codebook rows per block in NN kernel
#define BKNN 16       // k-chunk for NN kernel

// ---------------------------------------------------------------------------
// Device scratch (no allocations allowed)
// ---------------------------------------------------------------------------
__device__ unsigned long long g_best[BDIM];          // packed (dist_key<<32 | idx)
__device__ float g_codesT[CDIM * BDIM];              // codes transposed [k][m]
__device__ float g_prev[BDIM * CDIM];
__device__ float g_i  [BDIM * HDIM];
__device__ float g_h1 [BDIM * HDIM];
__device__ float g_s2 [BDIM * HDIM];
__device__ float g_s3 [BDIM * HDIM];
__device__ float g_h2 [BDIM * HDIM];
__device__ float g_acc[BDIM * HDIM];

// ---------------------------------------------------------------------------
// f32x2 packed-FMA helpers (FFMA2 — 2x fp32 throughput vs 3-reg FFMA)
// ---------------------------------------------------------------------------
__device__ __forceinline__ unsigned long long pack2f(float lo, float hi) {
    unsigned long long r;
    asm("mov.b64 %0, {%1, %2};"
        : "=l"(r) : "r"(__float_as_uint(lo)), "r"(__float_as_uint(hi)));
    return r;
}
__device__ __forceinline__ void unpack2f(unsigned long long v, float &lo, float &hi) {
    unsigned ulo, uhi;
    asm("mov.b64 {%0, %1}, %2;" : "=r"(ulo), "=r"(uhi) : "l"(v));
    lo = __uint_as_float(ulo);
    hi = __uint_as_float(uhi);
}
__device__ __forceinline__ void fma2(unsigned long long &d,
                                     unsigned long long a,
                                     unsigned long long b) {
    asm("fma.rn.f32x2 %0, %1, %2, %0;" : "+l"(d) : "l"(a), "l"(b));
}

// ---------------------------------------------------------------------------
// Small setup kernels
// ---------------------------------------------------------------------------
__global__ void k_init_best() {
    g_best[threadIdx.x] = 0xFFFFFFFFFFFFFFFFull;
}

// codesT[k*512 + m] = codes[m*256 + k]
__global__ void k_transpose_codes(const float* __restrict__ codes) {
    int t = blockIdx.x * blockDim.x + threadIdx.x;  // 0..131071
    int k = t >> 9;        // / 512
    int m = t & 511;
    g_codesT[t] = codes[m * CDIM + k];
}

// ---------------------------------------------------------------------------
// NN argmin kernel: dist'(n,m) = ||cb_n||^2 - 2 * dot(cb_n, code_m)
// Block: 32 codebook rows x all 512 codes. 256 threads:
//   r = tid>>5 (0..7)  -> 4 n rows each (n = n0 + 4r + i)
//   c = tid&31         -> 16 m each (m = 4c + 128j + e), as f32x2 pairs
// ---------------------------------------------------------------------------
__global__ __launch_bounds__(256)
void k_nn(const float* __restrict__ cb) {
    __shared__ __align__(16) union {
        float              As[BKNN][BDIM];   // codes chunk [k][m]  (32 KB)
        unsigned long long red[8][BDIM];     // reduction buffer    (32 KB)
    } u;
    __shared__ __align__(16) float Bs[BKNN][NTILE + 4];  // cb chunk [k][n]

    const int tid = threadIdx.x;
    const int r   = tid >> 5;
    const int c   = tid & 31;
    const int n0  = blockIdx.x * NTILE;

    unsigned long long acc[4][8];
    #pragma unroll
    for (int i = 0; i < 4; i++)
        #pragma unroll
        for (int p = 0; p < 8; p++) acc[i][p] = 0ull;  // packed (0.f, 0.f)
    float nrm[4] = {0.f, 0.f, 0.f, 0.f};

    for (int k0 = 0; k0 < CDIM; k0 += BKNN) {
        // Load codes chunk: 16 x 512 floats, straight float4 copies (pre-transposed)
        #pragma unroll
        for (int q = 0; q < 8; q++) {
            int idx = tid + q * 256;          // 0..2047 float4 slots
            int kk  = idx >> 7;               // 0..15
            int m4  = idx & 127;              // float4 index in row
            ((float4*)u.As[kk])[m4] =
                ((const float4*)&g_codesT[(size_t)(k0 + kk) * BDIM])[m4];
        }
        // Load codebook chunk: 32 rows x 16 k, transpose into Bs[k][n]
        if (tid < 128) {
            int nl = tid >> 2;
            int q  = tid & 3;
            float4 v = *(const float4*)&cb[(size_t)(n0 + nl) * CDIM + k0 + q * 4];
            Bs[q * 4 + 0][nl] = v.x;
            Bs[q * 4 + 1][nl] = v.y;
            Bs[q * 4 + 2][nl] = v.z;
            Bs[q * 4 + 3][nl] = v.w;
        }
        __syncthreads();

        #pragma unroll
        for (int k = 0; k < BKNN; k++) {
            float4 av = *(const float4*)&Bs[k][4 * r];
            nrm[0] = fmaf(av.x, av.x, nrm[0]);
            nrm[1] = fmaf(av.y, av.y, nrm[1]);
            nrm[2] = fmaf(av.z, av.z, nrm[2]);
            nrm[3] = fmaf(av.w, av.w, nrm[3]);
            unsigned long long a0 = pack2f(av.x, av.x);
            unsigned long long a1 = pack2f(av.y, av.y);
            unsigned long long a2 = pack2f(av.z, av.z);
            unsigned long long a3 = pack2f(av.w, av.w);
            #pragma unroll
            for (int j = 0; j < 4; j++) {
                const ulonglong2 b =
                    *(const ulonglong2*)&u.As[k][4 * c + 128 * j];
                fma2(acc[0][2 * j],     a0, b.x);
                fma2(acc[0][2 * j + 1], a0, b.y);
                fma2(acc[1][2 * j],     a1, b.x);
                fma2(acc[1][2 * j + 1], a1, b.y);
                fma2(acc[2][2 * j],     a2, b.x);
                fma2(acc[2][2 * j + 1], a2, b.y);
                fma2(acc[3][2 * j],     a3, b.x);
                fma2(acc[3][2 * j + 1], a3, b.y);
            }
        }
        __syncthreads();
    }

    // Per-thread min over its 4 n rows, for each of its 16 m; write red[r][m].
    #pragma unroll
    for (int j = 0; j < 4; j++) {
        #pragma unroll
        for (int p = 0; p < 2; p++) {
            int mb = 4 * c + 128 * j + 2 * p;
            unsigned long long best0 = 0xFFFFFFFFFFFFFFFFull;
            unsigned long long best1 = 0xFFFFFFFFFFFFFFFFull;
            #pragma unroll
            for (int i = 0; i < 4; i++) {
                float d0, d1;
                unpack2f(acc[i][2 * j + p], d0, d1);
                float dist0 = fmaf(-2.f, d0, nrm[i]);
                float dist1 = fmaf(-2.f, d1, nrm[i]);
                unsigned nidx = (unsigned)(n0 + 4 * r + i);
                unsigned kb0 = __float_as_uint(dist0);
                kb0 ^= (kb0 & 0x80000000u) ? 0xFFFFFFFFu : 0x80000000u;
                unsigned kb1 = __float_as_uint(dist1);
                kb1 ^= (kb1 & 0x80000000u) ? 0xFFFFFFFFu : 0x80000000u;
                unsigned long long e0 = ((unsigned long long)kb0 << 32) | nidx;
                unsigned long long e1 = ((unsigned long long)kb1 << 32) | nidx;
                if (e0 < best0) best0 = e0;
                if (e1 < best1) best1 = e1;
            }
            u.red[r][mb]     = best0;
            u.red[r][mb + 1] = best1;
        }
    }
    __syncthreads();

    // Final per-block reduce (each thread owns 2 m) + global atomicMin.
    #pragma unroll
    for (int s = 0; s < 2; s++) {
        int m = tid + s * 256;
        unsigned long long b = u.red[0][m];
        #pragma unroll
        for (int rr = 1; rr < 8; rr++) {
            unsigned long long v = u.red[rr][m];
            if (v < b) b = v;
        }
        atomicMin(&g_best[m], b);
    }
}

// prev[m,:] = codebook[best_idx[m], :]
__global__ void k_gather(const float* __restrict__ cb) {
    int m = blockIdx.x;
    unsigned idx = (unsigned)(g_best[m] & 0xFFFFFFFFull);
    g_prev[(size_t)m * CDIM + threadIdx.x] =
        cb[(size_t)idx * CDIM + threadIdx.x];
}

// ---------------------------------------------------------------------------
// Generic fused GEMM: Y(op)= act( (X [+X2]) @ W^T + bias )
// M fixed at 512. Tiles: 64x64x16, 256 threads, 4x4 per-thread.
// mode 0: Y = tanh(r);  mode 1: Y += tanh(r);  mode 2: Y = r
// ---------------------------------------------------------------------------
#define GBM 64
#define GBN 64
#define GBK 16

__global__ __launch_bounds__(256)
void k_gemm(const float* __restrict__ X, const float* __restrict__ X2,
            const float* __restrict__ W, const float* __restrict__ bias,
            float* __restrict__ Y, int Nv, int Kv, int mode) {
    __shared__ __align__(16) float Xs[GBK][GBM + 4];
    __shared__ __align__(16) float Ws[GBK][GBN + 4];

    const int tid = threadIdx.x;
    const int tx  = tid & 15;
    const int ty  = tid >> 4;
    const int m0  = blockIdx.y * GBM;
    const int n0  = blockIdx.x * GBN;

    float acc[4][4];
    #pragma unroll
    for (int i = 0; i < 4; i++)
        #pragma unroll
        for (int j = 0; j < 4; j++) acc[i][j] = 0.f;

    const int mr = tid >> 2;   // 0..63
    const int q  = tid & 3;    // 0..3

    for (int k0 = 0; k0 < Kv; k0 += GBK) {
        float4 xv = *(const float4*)&X[(size_t)(m0 + mr) * Kv + k0 + q * 4];
        if (X2) {
            float4 x2 = *(const float4*)&X2[(size_t)(m0 + mr) * Kv + k0 + q * 4];
            xv.x += x2.x; xv.y += x2.y; xv.z += x2.z; xv.w += x2.w;
        }
        Xs[q * 4 + 0][mr] = xv.x;
        Xs[q * 4 + 1][mr] = xv.y;
        Xs[q * 4 + 2][mr] = xv.z;
        Xs[q * 4 + 3][mr] = xv.w;

        float4 wv = *(const float4*)&W[(size_t)(n0 + mr) * Kv + k0 + q * 4];
        Ws[q * 4 + 0][mr] = wv.x;
        Ws[q * 4 + 1][mr] = wv.y;
        Ws[q * 4 + 2][mr] = wv.z;
        Ws[q * 4 + 3][mr] = wv.w;
        __syncthreads();

        #pragma unroll
        for (int k = 0; k < GBK; k++) {
            float4 a = *(const float4*)&Xs[k][ty * 4];
            float4 b = *(const float4*)&Ws[k][tx * 4];
            acc[0][0] = fmaf(a.x, b.x, acc[0][0]);
            acc[0][1] = fmaf(a.x, b.y, acc[0][1]);
            acc[0][2] = fmaf(a.x, b.z, acc[0][2]);
            acc[0][3] = fmaf(a.x, b.w, acc[0][3]);
            acc[1][0] = fmaf(a.y, b.x, acc[1][0]);
            acc[1][1] = fmaf(a.y, b.y, acc[1][1]);
            acc[1][2] = fmaf(a.y, b.z, acc[1][2]);
            acc[1][3] = fmaf(a.y, b.w, acc[1][3]);
            acc[2][0] = fmaf(a.z, b.x, acc[2][0]);
            acc[2][1] = fmaf(a.z, b.y, acc[2][1]);
            acc[2][2] = fmaf(a.z, b.z, acc[2][2]);
            acc[2][3] = fmaf(a.z, b.w, acc[2][3]);
            acc[3][0] = fmaf(a.w, b.x, acc[3][0]);
            acc[3][1] = fmaf(a.w, b.y, acc[3][1]);
            acc[3][2] = fmaf(a.w, b.z, acc[3][2]);
            acc[3][3] = fmaf(a.w, b.w, acc[3][3]);
        }
        __syncthreads();
    }

    #pragma unroll
    for (int i = 0; i < 4; i++) {
        int m = m0 + ty * 4 + i;
        #pragma unroll
        for (int j = 0; j < 4; j++) {
            int n = n0 + tx * 4 + j;
            float v = acc[i][j] + bias[n];
            if (mode != 2) v = tanhf(v);
            size_t o = (size_t)m * Nv + n;
            if (mode == 1) Y[o] += v;
            else           Y[o] = v;
        }
    }
}

// ---------------------------------------------------------------------------
// Launch
// ---------------------------------------------------------------------------
extern "C" void kernel_launch(void* const* d_in, const int* in_sizes, int n_in,
                              void* d_out, int out_size) {
    const float* codes = (const float*)d_in[0];
    const float* cb    = (const float*)d_in[1];
    const float* w_in  = (const float*)d_in[2];
    const float* b_in  = (const float*)d_in[3];
    const float* w_h1  = (const float*)d_in[4];
    const float* b_h1  = (const float*)d_in[5];
    const float* w_s2  = (const float*)d_in[6];
    const float* b_s2  = (const float*)d_in[7];
    const float* w_s3  = (const float*)d_in[8];
    const float* b_s3  = (const float*)d_in[9];
    const float* w_h2  = (const float*)d_in[10];
    const float* b_h2  = (const float*)d_in[11];
    const float* w_s1o = (const float*)d_in[12];
    const float* b_s1o = (const float*)d_in[13];
    const float* w_s2o = (const float*)d_in[14];
    const float* b_s2o = (const float*)d_in[15];
    const float* w_h3  = (const float*)d_in[16];
    const float* b_h3  = (const float*)d_in[17];
    const float* w_mu  = (const float*)d_in[18];
    const float* b_mu  = (const float*)d_in[19];
    const float* w_s   = (const float*)d_in[20];
    const float* b_s   = (const float*)d_in[21];
    float* out = (float*)d_out;  // [mu (512*256), logstd (512*256)]

    float *p_prev, *p_i, *p_h1, *p_s2, *p_s3, *p_h2, *p_acc;
    cudaGetSymbolAddress((void**)&p_prev, g_prev);
    cudaGetSymbolAddress((void**)&p_i,    g_i);
    cudaGetSymbolAddress((void**)&p_h1,   g_h1);
    cudaGetSymbolAddress((void**)&p_s2,   g_s2);
    cudaGetSymbolAddress((void**)&p_s3,   g_s3);
    cudaGetSymbolAddress((void**)&p_h2,   g_h2);
    cudaGetSymbolAddress((void**)&p_acc,  g_acc);

    // Stage 1: exact nearest neighbor
    k_transpose_codes<<<512, 256>>>(codes);
    k_init_best<<<1, 512>>>();
    k_nn<<<NCB / NTILE, 256>>>(cb);
    k_gather<<<BDIM, CDIM>>>(cb);

    // Stage 2: MLP
    dim3 gH(HDIM / GBN, BDIM / GBM);   // (16, 8)
    dim3 gC(CDIM / GBN, BDIM / GBM);   // (4, 8)
    k_gemm<<<gH, 256>>>(p_prev, nullptr, w_in,  b_in,  p_i,   HDIM, CDIM, 0);
    k_gemm<<<gH, 256>>>(p_i,    nullptr, w_h1,  b_h1,  p_h1,  HDIM, HDIM, 0);
    k_gemm<<<gH, 256>>>(p_h1,   nullptr, w_s2,  b_s2,  p_s2,  HDIM, HDIM, 0);
    k_gemm<<<gH, 256>>>(p_h1,   nullptr, w_s3,  b_s3,  p_s3,  HDIM, HDIM, 0);
    k_gemm<<<gH, 256>>>(p_h1,   p_s2,    w_h2,  b_h2,  p_h2,  HDIM, HDIM, 0);
    k_gemm<<<gH, 256>>>(p_h1,   nullptr, w_s1o, b_s1o, p_acc, HDIM, HDIM, 0);
    k_gemm<<<gH, 256>>>(p_h2,   nullptr, w_s2o, b_s2o, p_acc, HDIM, HDIM, 1);
    k_gemm<<<gH, 256>>>(p_h2,   p_s3,    w_h3,  b_h3,  p_acc, HDIM, HDIM, 1);
    k_gemm<<<gC, 256>>>(p_acc,  nullptr, w_mu,  b_mu,  out,                 CDIM, HDIM, 2);
    k_gemm<<<gC, 256>>>(p_acc,  nullptr, w_s,   b_s,   out + BDIM * CDIM,   CDIM, HDIM, 2);
}

// round 14
// speedup vs baseline: 2.2227x; 2.2227x over previous
#include <cuda_runtime.h>
#include <cuda_bf16.h>
#include <cstdint>
#include <math.h>

// Problem dims (fixed by the dataset)
#define BDIM 512      // batch (codes)
#define CDIM 256      // feature dim
#define HDIM 1024     // hidden dim
#define NCB  500000   // codebook rows
#define NROWS 64      // codebook rows per block
#define NBLK ((NCB + NROWS - 1) / NROWS)   // 7813

typedef unsigned long long u64;

// ---------------------------------------------------------------------------
// Device scratch (no allocations allowed)
// ---------------------------------------------------------------------------
__device__ u64 g_best[BDIM];
__device__ __align__(16) __nv_bfloat16 g_cA_hi[BDIM * CDIM];  // codes hi
__device__ __align__(16) __nv_bfloat16 g_cA_lo[BDIM * CDIM];  // codes lo
__device__ float g_prev[BDIM * CDIM];
__device__ float g_i  [BDIM * HDIM];
__device__ float g_h1 [BDIM * HDIM];
__device__ float g_s2 [BDIM * HDIM];
__device__ float g_s3 [BDIM * HDIM];
__device__ float g_h2 [BDIM * HDIM];
__device__ float g_acc[BDIM * HDIM];

// ---------------------------------------------------------------------------
// PTX helpers (baseline-family only: mma.sync / ldmatrix / cp.async)
// ---------------------------------------------------------------------------
__device__ __forceinline__ uint32_t smem_u32(const void* p) {
    uint32_t a;
    asm("{ .reg .u64 t; cvta.to.shared.u64 t, %1; cvt.u32.u64 %0, t; }"
        : "=r"(a) : "l"(p));
    return a;
}
__device__ __forceinline__ void ldsm4(uint32_t* r, uint32_t addr) {
    asm volatile("ldmatrix.sync.aligned.m8n8.x4.shared.b16 {%0,%1,%2,%3}, [%4];"
                 : "=r"(r[0]), "=r"(r[1]), "=r"(r[2]), "=r"(r[3]) : "r"(addr));
}
__device__ __forceinline__ void ldsm2(uint32_t* r, uint32_t addr) {
    asm volatile("ldmatrix.sync.aligned.m8n8.x2.shared.b16 {%0,%1}, [%2];"
                 : "=r"(r[0]), "=r"(r[1]) : "r"(addr));
}
__device__ __forceinline__ void mma_bf16(float* d, const uint32_t* a,
                                         const uint32_t* b) {
    asm volatile(
        "mma.sync.aligned.m16n8k16.row.col.f32.bf16.bf16.f32 "
        "{%0,%1,%2,%3}, {%4,%5,%6,%7}, {%8,%9}, {%0,%1,%2,%3};"
        : "+f"(d[0]), "+f"(d[1]), "+f"(d[2]), "+f"(d[3])
        : "r"(a[0]), "r"(a[1]), "r"(a[2]), "r"(a[3]), "r"(b[0]), "r"(b[1]));
}
__device__ __forceinline__ void cp16(uint32_t dst, const void* src) {
    asm volatile("cp.async.cg.shared.global [%0], [%1], 16;"
                 :: "r"(dst), "l"(src));
}
__device__ __forceinline__ void cp_commit_wait() {
    asm volatile("cp.async.commit_group;");
    asm volatile("cp.async.wait_group 0;");
}

__device__ __forceinline__ uint32_t split2(float x, float y, uint32_t& lo) {
    __nv_bfloat16 hx = __float2bfloat16_rn(x);
    __nv_bfloat16 hy = __float2bfloat16_rn(y);
    __nv_bfloat16 lx = __float2bfloat16_rn(x - __bfloat162float(hx));
    __nv_bfloat16 ly = __float2bfloat16_rn(y - __bfloat162float(hy));
    __nv_bfloat162 hh; hh.x = hx; hh.y = hy;
    __nv_bfloat162 ll; ll.x = lx; ll.y = ly;
    lo = *(uint32_t*)&ll;
    return *(uint32_t*)&hh;
}

__device__ __forceinline__ u64 dist_key(float dot, float nr, unsigned n) {
    float dist = fmaf(-2.f, dot, nr);
    unsigned kb = __float_as_uint(dist);
    kb ^= (kb & 0x80000000u) ? 0xFFFFFFFFu : 0x80000000u;
    return ((u64)kb << 32) | n;
}

// ---------------------------------------------------------------------------
// Setup kernels
// ---------------------------------------------------------------------------
__global__ void k_init_best() {
    g_best[threadIdx.x] = 0xFFFFFFFFFFFFFFFFull;
}

// codes -> plain [512][256] bf16 hi/lo images
__global__ void k_prep_codes(const float* __restrict__ codes) {
    int m = blockIdx.x, k = threadIdx.x;
    float x = codes[m * CDIM + k];
    __nv_bfloat16 h = __float2bfloat16_rn(x);
    __nv_bfloat16 l = __float2bfloat16_rn(x - __bfloat162float(h));
    g_cA_hi[m * CDIM + k] = h;
    g_cA_lo[m * CDIM + k] = l;
}

// ---------------------------------------------------------------------------
// NN argmin: bf16x3 via mma.sync.m16n8k16 (HMMA path, compute_103-safe)
// Block: 512 codes x 64 rows, K=256 in 4 chunks of 64. 512 threads, 16 warps:
// warp tile 64 codes x 32 rows (mg = w&7, ng = w>>3).
// SMEM rows padded to 144B -> conflict-free ldmatrix.
// ---------------------------------------------------------------------------
#define KC      64
#define KSTR    144                    // 128B row + 16B pad
#define OFF_AHI 0
#define OFF_ALO (512 * KSTR)           // 73728
#define OFF_BHI (2 * 512 * KSTR)       // 147456
#define OFF_BLO (OFF_BHI + NROWS * KSTR)
#define OFF_NRM (OFF_BLO + NROWS * KSTR)
#define SM_TOTAL (OFF_NRM + NROWS * 4) // 166144

__global__ __launch_bounds__(512, 1)
void k_nn_mma(const float* __restrict__ cb) {
    extern __shared__ char smem[];
    const uint32_t sb = smem_u32(smem);
    const int tid  = threadIdx.x;
    const int wid  = tid >> 5;
    const int lane = tid & 31;
    const int mg   = wid & 7;    // code group  (64 codes)
    const int ng   = wid >> 3;   // row group   (32 rows)
    const int n0   = blockIdx.x * NROWS;

    // B-load role: thread owns row r, 8 k-columns at q*8
    const int r = tid >> 3;
    const int q = tid & 7;
    const int grow = min(n0 + r, NCB - 1);
    const float4* bsrc = (const float4*)(cb + (size_t)grow * CDIM + q * 8);

    // ldmatrix source addresses (fixed parts)
    const uint32_t aHiRow = sb + OFF_AHI + (mg * 64 + (lane & 15)) * KSTR +
                            ((lane >> 4) << 4);
    const uint32_t aLoRow = aHiRow + (OFF_ALO - OFF_AHI);
    const uint32_t bHiRow = sb + OFF_BHI + (ng * 32 + (lane & 7)) * KSTR +
                            (((lane >> 3) & 1) << 4);
    const uint32_t bLoRow = bHiRow + (OFF_BLO - OFF_BHI);

    float acc[4][4][4];
    #pragma unroll
    for (int a = 0; a < 4; a++)
        #pragma unroll
        for (int b = 0; b < 4; b++)
            #pragma unroll
            for (int e = 0; e < 4; e++) acc[a][b][e] = 0.f;
    float sq = 0.f;

    const char* aHiG = (const char*)g_cA_hi;
    const char* aLoG = (const char*)g_cA_lo;

    for (int c = 0; c < 4; c++) {
        __syncthreads();   // previous chunk's mma reads done

        // --- A: cp.async codes chunk (hi+lo), 16 pieces/thread ---
        #pragma unroll
        for (int j = 0; j < 8; j++) {
            int lin = j * 512 + tid;        // 0..4095
            int row = lin >> 3;
            int qq  = lin & 7;
            uint32_t d = sb + OFF_AHI + row * KSTR + qq * 16;
            const char* s = aHiG + row * 512 + c * 128 + qq * 16;
            cp16(d, s);
            cp16(d + (OFF_ALO - OFF_AHI), s + (aLoG - aHiG));
        }

        // --- B: LDG fp32, split, STS; accumulate exact fp32 norms ---
        float4 v0 = bsrc[c * 16];
        float4 v1 = bsrc[c * 16 + 1];
        sq = fmaf(v0.x, v0.x, sq); sq = fmaf(v0.y, v0.y, sq);
        sq = fmaf(v0.z, v0.z, sq); sq = fmaf(v0.w, v0.w, sq);
        sq = fmaf(v1.x, v1.x, sq); sq = fmaf(v1.y, v1.y, sq);
        sq = fmaf(v1.z, v1.z, sq); sq = fmaf(v1.w, v1.w, sq);
        uint4 h, l;
        h.x = split2(v0.x, v0.y, l.x);
        h.y = split2(v0.z, v0.w, l.y);
        h.z = split2(v1.x, v1.y, l.z);
        h.w = split2(v1.z, v1.w, l.w);
        *(uint4*)(smem + OFF_BHI + r * KSTR + q * 16) = h;
        *(uint4*)(smem + OFF_BLO + r * KSTR + q * 16) = l;

        cp_commit_wait();
        __syncthreads();

        // --- MMA: 4 k16 steps x 4 mtiles x 4 ntiles x 3 terms ---
        #pragma unroll
        for (int s = 0; s < 4; s++) {
            uint32_t bh[4][2], bl[4][2];
            #pragma unroll
            for (int nt = 0; nt < 4; nt++) {
                ldsm2(bh[nt], bHiRow + nt * 8 * KSTR + s * 32);
                ldsm2(bl[nt], bLoRow + nt * 8 * KSTR + s * 32);
            }
            #pragma unroll
            for (int mt = 0; mt < 4; mt++) {
                uint32_t af[4];
                ldsm4(af, aHiRow + mt * 16 * KSTR + s * 32);
                #pragma unroll
                for (int nt = 0; nt < 4; nt++) mma_bf16(acc[mt][nt], af, bh[nt]);
                #pragma unroll
                for (int nt = 0; nt < 4; nt++) mma_bf16(acc[mt][nt], af, bl[nt]);
                ldsm4(af, aLoRow + mt * 16 * KSTR + s * 32);
                #pragma unroll
                for (int nt = 0; nt < 4; nt++) mma_bf16(acc[mt][nt], af, bh[nt]);
            }
        }
    }

    // Row norms: reduce over the 8 lanes sharing a row, publish to smem
    sq += __shfl_xor_sync(0xFFFFFFFFu, sq, 1);
    sq += __shfl_xor_sync(0xFFFFFFFFu, sq, 2);
    sq += __shfl_xor_sync(0xFFFFFFFFu, sq, 4);
    float* nrm = (float*)(smem + OFF_NRM);
    if ((tid & 7) == 0) nrm[r] = sq;
    __syncthreads();

    // Epilogue: dist = nrm - 2*dot; packed-key argmin
    const int g = lane >> 2;
    const int i = lane & 3;
    #pragma unroll
    for (int mt = 0; mt < 4; mt++) {
        u64 b0 = 0xFFFFFFFFFFFFFFFFull;   // code row g
        u64 b1 = 0xFFFFFFFFFFFFFFFFull;   // code row g+8
        #pragma unroll
        for (int nt = 0; nt < 4; nt++) {
            int nl = ng * 32 + nt * 8 + 2 * i;
            int n  = n0 + nl;
            const float* d = acc[mt][nt];
            if (n < NCB) {
                u64 e = dist_key(d[0], nrm[nl], (unsigned)n);
                if (e < b0) b0 = e;
                e = dist_key(d[2], nrm[nl], (unsigned)n);
                if (e < b1) b1 = e;
            }
            if (n + 1 < NCB) {
                u64 e = dist_key(d[1], nrm[nl + 1], (unsigned)(n + 1));
                if (e < b0) b0 = e;
                e = dist_key(d[3], nrm[nl + 1], (unsigned)(n + 1));
                if (e < b1) b1 = e;
            }
        }
        #pragma unroll
        for (int m = 1; m <= 2; m++) {
            u64 o0 = __shfl_xor_sync(0xFFFFFFFFu, b0, m);
            u64 o1 = __shfl_xor_sync(0xFFFFFFFFu, b1, m);
            if (o0 < b0) b0 = o0;
            if (o1 < b1) b1 = o1;
        }
        if (i == 0) {
            int code = mg * 64 + mt * 16 + g;
            atomicMin(&g_best[code], b0);
            atomicMin(&g_best[code + 8], b1);
        }
    }
}

// prev[m,:] = codebook[best_idx[m], :]
__global__ void k_gather(const float* __restrict__ cb) {
    int m = blockIdx.x;
    unsigned idx = (unsigned)(g_best[m] & 0xFFFFFFFFull);
    g_prev[(size_t)m * CDIM + threadIdx.x] =
        cb[(size_t)idx * CDIM + threadIdx.x];
}

// ---------------------------------------------------------------------------
// Generic fused GEMM: Y(op)= act( (X [+X2]) @ W^T + bias )
// Tiles: 64x64x16, 256 threads, 4x4 per-thread.
// mode 0: Y = tanh(r);  mode 1: Y += tanh(r);  mode 2: Y = r
// ---------------------------------------------------------------------------
#define GBM 64
#define GBN 64
#define GBK 16

__global__ __launch_bounds__(256)
void k_gemm(const float* __restrict__ X, const float* __restrict__ X2,
            const float* __restrict__ W, const float* __restrict__ bias,
            float* __restrict__ Y, int Nv, int Kv, int mode) {
    __shared__ __align__(16) float Xs[GBK][GBM + 4];
    __shared__ __align__(16) float Ws[GBK][GBN + 4];

    const int tid = threadIdx.x;
    const int tx  = tid & 15;
    const int ty  = tid >> 4;
    const int m0  = blockIdx.y * GBM;
    const int n0  = blockIdx.x * GBN;

    float acc[4][4];
    #pragma unroll
    for (int i = 0; i < 4; i++)
        #pragma unroll
        for (int j = 0; j < 4; j++) acc[i][j] = 0.f;

    const int mr = tid >> 2;
    const int q  = tid & 3;

    for (int k0 = 0; k0 < Kv; k0 += GBK) {
        float4 xv = *(const float4*)&X[(size_t)(m0 + mr) * Kv + k0 + q * 4];
        if (X2) {
            float4 x2 = *(const float4*)&X2[(size_t)(m0 + mr) * Kv + k0 + q * 4];
            xv.x += x2.x; xv.y += x2.y; xv.z += x2.z; xv.w += x2.w;
        }
        Xs[q * 4 + 0][mr] = xv.x;
        Xs[q * 4 + 1][mr] = xv.y;
        Xs[q * 4 + 2][mr] = xv.z;
        Xs[q * 4 + 3][mr] = xv.w;

        float4 wv = *(const float4*)&W[(size_t)(n0 + mr) * Kv + k0 + q * 4];
        Ws[q * 4 + 0][mr] = wv.x;
        Ws[q * 4 + 1][mr] = wv.y;
        Ws[q * 4 + 2][mr] = wv.z;
        Ws[q * 4 + 3][mr] = wv.w;
        __syncthreads();

        #pragma unroll
        for (int k = 0; k < GBK; k++) {
            float4 a = *(const float4*)&Xs[k][ty * 4];
            float4 b = *(const float4*)&Ws[k][tx * 4];
            acc[0][0] = fmaf(a.x, b.x, acc[0][0]);
            acc[0][1] = fmaf(a.x, b.y, acc[0][1]);
            acc[0][2] = fmaf(a.x, b.z, acc[0][2]);
            acc[0][3] = fmaf(a.x, b.w, acc[0][3]);
            acc[1][0] = fmaf(a.y, b.x, acc[1][0]);
            acc[1][1] = fmaf(a.y, b.y, acc[1][1]);
            acc[1][2] = fmaf(a.y, b.z, acc[1][2]);
            acc[1][3] = fmaf(a.y, b.w, acc[1][3]);
            acc[2][0] = fmaf(a.z, b.x, acc[2][0]);
            acc[2][1] = fmaf(a.z, b.y, acc[2][1]);
            acc[2][2] = fmaf(a.z, b.z, acc[2][2]);
            acc[2][3] = fmaf(a.z, b.w, acc[2][3]);
            acc[3][0] = fmaf(a.w, b.x, acc[3][0]);
            acc[3][1] = fmaf(a.w, b.y, acc[3][1]);
            acc[3][2] = fmaf(a.w, b.z, acc[3][2]);
            acc[3][3] = fmaf(a.w, b.w, acc[3][3]);
        }
        __syncthreads();
    }

    #pragma unroll
    for (int i = 0; i < 4; i++) {
        int m = m0 + ty * 4 + i;
        #pragma unroll
        for (int j = 0; j < 4; j++) {
            int n = n0 + tx * 4 + j;
            float v = acc[i][j] + bias[n];
            if (mode != 2) v = tanhf(v);
            size_t o = (size_t)m * Nv + n;
            if (mode == 1) Y[o] += v;
            else           Y[o] = v;
        }
    }
}

// ---------------------------------------------------------------------------
// Launch
// ---------------------------------------------------------------------------
extern "C" void kernel_launch(void* const* d_in, const int* in_sizes, int n_in,
                              void* d_out, int out_size) {
    const float* codes = (const float*)d_in[0];
    const float* cb    = (const float*)d_in[1];
    const float* w_in  = (const float*)d_in[2];
    const float* b_in  = (const float*)d_in[3];
    const float* w_h1  = (const float*)d_in[4];
    const float* b_h1  = (const float*)d_in[5];
    const float* w_s2  = (const float*)d_in[6];
    const float* b_s2  = (const float*)d_in[7];
    const float* w_s3  = (const float*)d_in[8];
    const float* b_s3  = (const float*)d_in[9];
    const float* w_h2  = (const float*)d_in[10];
    const float* b_h2  = (const float*)d_in[11];
    const float* w_s1o = (const float*)d_in[12];
    const float* b_s1o = (const float*)d_in[13];
    const float* w_s2o = (const float*)d_in[14];
    const float* b_s2o = (const float*)d_in[15];
    const float* w_h3  = (const float*)d_in[16];
    const float* b_h3  = (const float*)d_in[17];
    const float* w_mu  = (const float*)d_in[18];
    const float* b_mu  = (const float*)d_in[19];
    const float* w_s   = (const float*)d_in[20];
    const float* b_s   = (const float*)d_in[21];
    float* out = (float*)d_out;  // [mu (512*256), logstd (512*256)]

    float *p_prev, *p_i, *p_h1, *p_s2, *p_s3, *p_h2, *p_acc;
    cudaGetSymbolAddress((void**)&p_prev, g_prev);
    cudaGetSymbolAddress((void**)&p_i,    g_i);
    cudaGetSymbolAddress((void**)&p_h1,   g_h1);
    cudaGetSymbolAddress((void**)&p_s2,   g_s2);
    cudaGetSymbolAddress((void**)&p_s3,   g_s3);
    cudaGetSymbolAddress((void**)&p_h2,   g_h2);
    cudaGetSymbolAddress((void**)&p_acc,  g_acc);

    cudaFuncSetAttribute(k_nn_mma,
                         cudaFuncAttributeMaxDynamicSharedMemorySize, SM_TOTAL);

    // Stage 1: exact-quality nearest neighbor via bf16x3 mma.sync
    k_prep_codes<<<BDIM, CDIM>>>(codes);
    k_init_best<<<1, 512>>>();
    k_nn_mma<<<NBLK, 512, SM_TOTAL>>>(cb);
    k_gather<<<BDIM, CDIM>>>(cb);

    // Stage 2: MLP
    dim3 gH(HDIM / GBN, BDIM / GBM);   // (16, 8)
    dim3 gC(CDIM / GBN, BDIM / GBM);   // (4, 8)
    k_gemm<<<gH, 256>>>(p_prev, nullptr, w_in,  b_in,  p_i,   HDIM, CDIM, 0);
    k_gemm<<<gH, 256>>>(p_i,    nullptr, w_h1,  b_h1,  p_h1,  HDIM, HDIM, 0);
    k_gemm<<<gH, 256>>>(p_h1,   nullptr, w_s2,  b_s2,  p_s2,  HDIM, HDIM, 0);
    k_gemm<<<gH, 256>>>(p_h1,   nullptr, w_s3,  b_s3,  p_s3,  HDIM, HDIM, 0);
    k_gemm<<<gH, 256>>>(p_h1,   p_s2,    w_h2,  b_h2,  p_h2,  HDIM, HDIM, 0);
    k_gemm<<<gH, 256>>>(p_h1,   nullptr, w_s1o, b_s1o, p_acc, HDIM, HDIM, 0);
    k_gemm<<<gH, 256>>>(p_h2,   nullptr, w_s2o, b_s2o, p_acc, HDIM, HDIM, 1);
    k_gemm<<<gH, 256>>>(p_h2,   p_s3,    w_h3,  b_h3,  p_acc, HDIM, HDIM, 1);
    k_gemm<<<gC, 256>>>(p_acc,  nullptr, w_mu,  b_mu,  out,               CDIM, HDIM, 2);
    k_gemm<<<gC, 256>>>(p_acc,  nullptr, w_s,   b_s,   out + BDIM * CDIM, CDIM, HDIM, 2);
}

// round 15
// speedup vs baseline: 2.2293x; 1.0030x over previous
#include <cuda_runtime.h>
#include <cuda_bf16.h>
#include <cstdint>
#include <math.h>

// Problem dims (fixed by the dataset)
#define BDIM 512      // batch (codes)
#define CDIM 256      // feature dim
#define HDIM 1024     // hidden dim
#define NCB  500000   // codebook rows
#define NROWS 64      // codebook rows per block
#define NBLK ((NCB + NROWS - 1) / NROWS)   // 7813

typedef unsigned long long u64;

// ---------------------------------------------------------------------------
// Device scratch (no allocations allowed)
// ---------------------------------------------------------------------------
__device__ u64 g_best[BDIM];
__device__ __align__(16) __nv_bfloat16 g_cA_hi[BDIM * CDIM];  // codes hi
__device__ __align__(16) __nv_bfloat16 g_cA_lo[BDIM * CDIM];  // codes lo
__device__ float g_prev[BDIM * CDIM];
__device__ float g_i  [BDIM * HDIM];
__device__ float g_h1 [BDIM * HDIM];
__device__ float g_s2 [BDIM * HDIM];
__device__ float g_s3 [BDIM * HDIM];
__device__ float g_h2 [BDIM * HDIM];
__device__ float g_acc[BDIM * HDIM];

// ---------------------------------------------------------------------------
// PTX helpers (baseline-family only: mma.sync / ldmatrix / cp.async)
// ---------------------------------------------------------------------------
__device__ __forceinline__ uint32_t smem_u32(const void* p) {
    uint32_t a;
    asm("{ .reg .u64 t; cvta.to.shared.u64 t, %1; cvt.u32.u64 %0, t; }"
        : "=r"(a) : "l"(p));
    return a;
}
__device__ __forceinline__ void ldsm4(uint32_t* r, uint32_t addr) {
    asm volatile("ldmatrix.sync.aligned.m8n8.x4.shared.b16 {%0,%1,%2,%3}, [%4];"
                 : "=r"(r[0]), "=r"(r[1]), "=r"(r[2]), "=r"(r[3]) : "r"(addr));
}
__device__ __forceinline__ void ldsm2(uint32_t* r, uint32_t addr) {
    asm volatile("ldmatrix.sync.aligned.m8n8.x2.shared.b16 {%0,%1}, [%2];"
                 : "=r"(r[0]), "=r"(r[1]) : "r"(addr));
}
__device__ __forceinline__ void mma_bf16(float* d, const uint32_t* a,
                                         const uint32_t* b) {
    asm volatile(
        "mma.sync.aligned.m16n8k16.row.col.f32.bf16.bf16.f32 "
        "{%0,%1,%2,%3}, {%4,%5,%6,%7}, {%8,%9}, {%0,%1,%2,%3};"
        : "+f"(d[0]), "+f"(d[1]), "+f"(d[2]), "+f"(d[3])
        : "r"(a[0]), "r"(a[1]), "r"(a[2]), "r"(a[3]), "r"(b[0]), "r"(b[1]));
}
__device__ __forceinline__ void cp16(uint32_t dst, const void* src) {
    asm volatile("cp.async.cg.shared.global [%0], [%1], 16;"
                 :: "r"(dst), "l"(src));
}
__device__ __forceinline__ void cp_commit_wait() {
    asm volatile("cp.async.commit_group;");
    asm volatile("cp.async.wait_group 0;");
}

__device__ __forceinline__ uint32_t split2(float x, float y, uint32_t& lo) {
    __nv_bfloat16 hx = __float2bfloat16_rn(x);
    __nv_bfloat16 hy = __float2bfloat16_rn(y);
    __nv_bfloat16 lx = __float2bfloat16_rn(x - __bfloat162float(hx));
    __nv_bfloat16 ly = __float2bfloat16_rn(y - __bfloat162float(hy));
    __nv_bfloat162 hh; hh.x = hx; hh.y = hy;
    __nv_bfloat162 ll; ll.x = lx; ll.y = ly;
    lo = *(uint32_t*)&ll;
    return *(uint32_t*)&hh;
}

__device__ __forceinline__ u64 dist_key(float dot, float nr, unsigned n) {
    float dist = fmaf(-2.f, dot, nr);
    unsigned kb = __float_as_uint(dist);
    kb ^= (kb & 0x80000000u) ? 0xFFFFFFFFu : 0x80000000u;
    return ((u64)kb << 32) | n;
}

// ---------------------------------------------------------------------------
// Setup kernels
// ---------------------------------------------------------------------------
__global__ void k_init_best() {
    g_best[threadIdx.x] = 0xFFFFFFFFFFFFFFFFull;
}

// codes -> plain [512][256] bf16 hi/lo images
__global__ void k_prep_codes(const float* __restrict__ codes) {
    int m = blockIdx.x, k = threadIdx.x;
    float x = codes[m * CDIM + k];
    __nv_bfloat16 h = __float2bfloat16_rn(x);
    __nv_bfloat16 l = __float2bfloat16_rn(x - __bfloat162float(h));
    g_cA_hi[m * CDIM + k] = h;
    g_cA_lo[m * CDIM + k] = l;
}

// ---------------------------------------------------------------------------
// NN argmin: bf16x3 via mma.sync.m16n8k16 (HMMA path, compute_103-safe)
// Block: 512 codes x 64 rows, K=256 in 4 chunks of 64. 512 threads, 16 warps:
// warp tile 64 codes x 32 rows (mg = w&7, ng = w>>3).
// SMEM rows padded to 144B -> conflict-free ldmatrix.
// ---------------------------------------------------------------------------
#define KC      64
#define KSTR    144                    // 128B row + 16B pad
#define OFF_AHI 0
#define OFF_ALO (512 * KSTR)           // 73728
#define OFF_BHI (2 * 512 * KSTR)       // 147456
#define OFF_BLO (OFF_BHI + NROWS * KSTR)
#define OFF_NRM (OFF_BLO + NROWS * KSTR)
#define SM_TOTAL (OFF_NRM + NROWS * 4) // 166144

__global__ __launch_bounds__(512, 1)
void k_nn_mma(const float* __restrict__ cb) {
    extern __shared__ char smem[];
    const uint32_t sb = smem_u32(smem);
    const int tid  = threadIdx.x;
    const int wid  = tid >> 5;
    const int lane = tid & 31;
    const int mg   = wid & 7;    // code group  (64 codes)
    const int ng   = wid >> 3;   // row group   (32 rows)
    const int n0   = blockIdx.x * NROWS;

    // B-load role: thread owns row r, 8 k-columns at q*8
    const int r = tid >> 3;
    const int q = tid & 7;
    const int grow = min(n0 + r, NCB - 1);
    const float4* bsrc = (const float4*)(cb + (size_t)grow * CDIM + q * 8);

    // ldmatrix source addresses (fixed parts)
    const uint32_t aHiRow = sb + OFF_AHI + (mg * 64 + (lane & 15)) * KSTR +
                            ((lane >> 4) << 4);
    const uint32_t aLoRow = aHiRow + (OFF_ALO - OFF_AHI);
    const uint32_t bHiRow = sb + OFF_BHI + (ng * 32 + (lane & 7)) * KSTR +
                            (((lane >> 3) & 1) << 4);
    const uint32_t bLoRow = bHiRow + (OFF_BLO - OFF_BHI);

    float acc[4][4][4];
    #pragma unroll
    for (int a = 0; a < 4; a++)
        #pragma unroll
        for (int b = 0; b < 4; b++)
            #pragma unroll
            for (int e = 0; e < 4; e++) acc[a][b][e] = 0.f;
    float sq = 0.f;

    const char* aHiG = (const char*)g_cA_hi;
    const char* aLoG = (const char*)g_cA_lo;

    for (int c = 0; c < 4; c++) {
        __syncthreads();   // previous chunk's mma reads done

        // --- A: cp.async codes chunk (hi+lo), 16 pieces/thread ---
        #pragma unroll
        for (int j = 0; j < 8; j++) {
            int lin = j * 512 + tid;        // 0..4095
            int row = lin >> 3;
            int qq  = lin & 7;
            uint32_t d = sb + OFF_AHI + row * KSTR + qq * 16;
            const char* s = aHiG + row * 512 + c * 128 + qq * 16;
            cp16(d, s);
            cp16(d + (OFF_ALO - OFF_AHI), s + (aLoG - aHiG));
        }

        // --- B: LDG fp32, split, STS; accumulate exact fp32 norms ---
        float4 v0 = bsrc[c * 16];
        float4 v1 = bsrc[c * 16 + 1];
        sq = fmaf(v0.x, v0.x, sq); sq = fmaf(v0.y, v0.y, sq);
        sq = fmaf(v0.z, v0.z, sq); sq = fmaf(v0.w, v0.w, sq);
        sq = fmaf(v1.x, v1.x, sq); sq = fmaf(v1.y, v1.y, sq);
        sq = fmaf(v1.z, v1.z, sq); sq = fmaf(v1.w, v1.w, sq);
        uint4 h, l;
        h.x = split2(v0.x, v0.y, l.x);
        h.y = split2(v0.z, v0.w, l.y);
        h.z = split2(v1.x, v1.y, l.z);
        h.w = split2(v1.z, v1.w, l.w);
        *(uint4*)(smem + OFF_BHI + r * KSTR + q * 16) = h;
        *(uint4*)(smem + OFF_BLO + r * KSTR + q * 16) = l;

        cp_commit_wait();
        __syncthreads();

        // --- MMA: 4 k16 steps x 4 mtiles x 4 ntiles x 3 terms ---
        #pragma unroll
        for (int s = 0; s < 4; s++) {
            uint32_t bh[4][2], bl[4][2];
            #pragma unroll
            for (int nt = 0; nt < 4; nt++) {
                ldsm2(bh[nt], bHiRow + nt * 8 * KSTR + s * 32);
                ldsm2(bl[nt], bLoRow + nt * 8 * KSTR + s * 32);
            }
            #pragma unroll
            for (int mt = 0; mt < 4; mt++) {
                uint32_t af[4];
                ldsm4(af, aHiRow + mt * 16 * KSTR + s * 32);
                #pragma unroll
                for (int nt = 0; nt < 4; nt++) mma_bf16(acc[mt][nt], af, bh[nt]);
                #pragma unroll
                for (int nt = 0; nt < 4; nt++) mma_bf16(acc[mt][nt], af, bl[nt]);
                ldsm4(af, aLoRow + mt * 16 * KSTR + s * 32);
                #pragma unroll
                for (int nt = 0; nt < 4; nt++) mma_bf16(acc[mt][nt], af, bh[nt]);
            }
        }
    }

    // Row norms: reduce over the 8 lanes sharing a row, publish to smem
    sq += __shfl_xor_sync(0xFFFFFFFFu, sq, 1);
    sq += __shfl_xor_sync(0xFFFFFFFFu, sq, 2);
    sq += __shfl_xor_sync(0xFFFFFFFFu, sq, 4);
    float* nrm = (float*)(smem + OFF_NRM);
    if ((tid & 7) == 0) nrm[r] = sq;
    __syncthreads();

    // Epilogue: dist = nrm - 2*dot; packed-key argmin
    const int g = lane >> 2;
    const int i = lane & 3;
    #pragma unroll
    for (int mt = 0; mt < 4; mt++) {
        u64 b0 = 0xFFFFFFFFFFFFFFFFull;   // code row g
        u64 b1 = 0xFFFFFFFFFFFFFFFFull;   // code row g+8
        #pragma unroll
        for (int nt = 0; nt < 4; nt++) {
            int nl = ng * 32 + nt * 8 + 2 * i;
            int n  = n0 + nl;
            const float* d = acc[mt][nt];
            if (n < NCB) {
                u64 e = dist_key(d[0], nrm[nl], (unsigned)n);
                if (e < b0) b0 = e;
                e = dist_key(d[2], nrm[nl], (unsigned)n);
                if (e < b1) b1 = e;
            }
            if (n + 1 < NCB) {
                u64 e = dist_key(d[1], nrm[nl + 1], (unsigned)(n + 1));
                if (e < b0) b0 = e;
                e = dist_key(d[3], nrm[nl + 1], (unsigned)(n + 1));
                if (e < b1) b1 = e;
            }
        }
        #pragma unroll
        for (int m = 1; m <= 2; m++) {
            u64 o0 = __shfl_xor_sync(0xFFFFFFFFu, b0, m);
            u64 o1 = __shfl_xor_sync(0xFFFFFFFFu, b1, m);
            if (o0 < b0) b0 = o0;
            if (o1 < b1) b1 = o1;
        }
        if (i == 0) {
            int code = mg * 64 + mt * 16 + g;
            atomicMin(&g_best[code], b0);
            atomicMin(&g_best[code + 8], b1);
        }
    }
}

// prev[m,:] = codebook[best_idx[m], :]
__global__ void k_gather(const float* __restrict__ cb) {
    int m = blockIdx.x;
    unsigned idx = (unsigned)(g_best[m] & 0xFFFFFFFFull);
    g_prev[(size_t)m * CDIM + threadIdx.x] =
        cb[(size_t)idx * CDIM + threadIdx.x];
}

// ---------------------------------------------------------------------------
// Generic fused GEMM: Y(op)= act( (X [+X2]) @ W^T + bias )
// Tiles: 64x64x16, 256 threads, 4x4 per-thread.
// mode 0: Y = tanh(r);  mode 1: Y += tanh(r);  mode 2: Y = r
// ---------------------------------------------------------------------------
#define GBM 64
#define GBN 64
#define GBK 16

__global__ __launch_bounds__(256)
void k_gemm(const float* __restrict__ X, const float* __restrict__ X2,
            const float* __restrict__ W, const float* __restrict__ bias,
            float* __restrict__ Y, int Nv, int Kv, int mode) {
    __shared__ __align__(16) float Xs[GBK][GBM + 4];
    __shared__ __align__(16) float Ws[GBK][GBN + 4];

    const int tid = threadIdx.x;
    const int tx  = tid & 15;
    const int ty  = tid >> 4;
    const int m0  = blockIdx.y * GBM;
    const int n0  = blockIdx.x * GBN;

    float acc[4][4];
    #pragma unroll
    for (int i = 0; i < 4; i++)
        #pragma unroll
        for (int j = 0; j < 4; j++) acc[i][j] = 0.f;

    const int mr = tid >> 2;
    const int q  = tid & 3;

    for (int k0 = 0; k0 < Kv; k0 += GBK) {
        float4 xv = *(const float4*)&X[(size_t)(m0 + mr) * Kv + k0 + q * 4];
        if (X2) {
            float4 x2 = *(const float4*)&X2[(size_t)(m0 + mr) * Kv + k0 + q * 4];
            xv.x += x2.x; xv.y += x2.y; xv.z += x2.z; xv.w += x2.w;
        }
        Xs[q * 4 + 0][mr] = xv.x;
        Xs[q * 4 + 1][mr] = xv.y;
        Xs[q * 4 + 2][mr] = xv.z;
        Xs[q * 4 + 3][mr] = xv.w;

        float4 wv = *(const float4*)&W[(size_t)(n0 + mr) * Kv + k0 + q * 4];
        Ws[q * 4 + 0][mr] = wv.x;
        Ws[q * 4 + 1][mr] = wv.y;
        Ws[q * 4 + 2][mr] = wv.z;
        Ws[q * 4 + 3][mr] = wv.w;
        __syncthreads();

        #pragma unroll
        for (int k = 0; k < GBK; k++) {
            float4 a = *(const float4*)&Xs[k][ty * 4];
            float4 b = *(const float4*)&Ws[k][tx * 4];
            acc[0][0] = fmaf(a.x, b.x, acc[0][0]);
            acc[0][1] = fmaf(a.x, b.y, acc[0][1]);
            acc[0][2] = fmaf(a.x, b.z, acc[0][2]);
            acc[0][3] = fmaf(a.x, b.w, acc[0][3]);
            acc[1][0] = fmaf(a.y, b.x, acc[1][0]);
            acc[1][1] = fmaf(a.y, b.y, acc[1][1]);
            acc[1][2] = fmaf(a.y, b.z, acc[1][2]);
            acc[1][3] = fmaf(a.y, b.w, acc[1][3]);
            acc[2][0] = fmaf(a.z, b.x, acc[2][0]);
            acc[2][1] = fmaf(a.z, b.y, acc[2][1]);
            acc[2][2] = fmaf(a.z, b.z, acc[2][2]);
            acc[2][3] = fmaf(a.z, b.w, acc[2][3]);
            acc[3][0] = fmaf(a.w, b.x, acc[3][0]);
            acc[3][1] = fmaf(a.w, b.y, acc[3][1]);
            acc[3][2] = fmaf(a.w, b.z, acc[3][2]);
            acc[3][3] = fmaf(a.w, b.w, acc[3][3]);
        }
        __syncthreads();
    }

    #pragma unroll
    for (int i = 0; i < 4; i++) {
        int m = m0 + ty * 4 + i;
        #pragma unroll
        for (int j = 0; j < 4; j++) {
            int n = n0 + tx * 4 + j;
            float v = acc[i][j] + bias[n];
            if (mode != 2) v = tanhf(v);
            size_t o = (size_t)m * Nv + n;
            if (mode == 1) Y[o] += v;
            else           Y[o] = v;
        }
    }
}

// ---------------------------------------------------------------------------
// Launch
// ---------------------------------------------------------------------------
extern "C" void kernel_launch(void* const* d_in, const int* in_sizes, int n_in,
                              void* d_out, int out_size) {
    const float* codes = (const float*)d_in[0];
    const float* cb    = (const float*)d_in[1];
    const float* w_in  = (const float*)d_in[2];
    const float* b_in  = (const float*)d_in[3];
    const float* w_h1  = (const float*)d_in[4];
    const float* b_h1  = (const float*)d_in[5];
    const float* w_s2  = (const float*)d_in[6];
    const float* b_s2  = (const float*)d_in[7];
    const float* w_s3  = (const float*)d_in[8];
    const float* b_s3  = (const float*)d_in[9];
    const float* w_h2  = (const float*)d_in[10];
    const float* b_h2  = (const float*)d_in[11];
    const float* w_s1o = (const float*)d_in[12];
    const float* b_s1o = (const float*)d_in[13];
    const float* w_s2o = (const float*)d_in[14];
    const float* b_s2o = (const float*)d_in[15];
    const float* w_h3  = (const float*)d_in[16];
    const float* b_h3  = (const float*)d_in[17];
    const float* w_mu  = (const float*)d_in[18];
    const float* b_mu  = (const float*)d_in[19];
    const float* w_s   = (const float*)d_in[20];
    const float* b_s   = (const float*)d_in[21];
    float* out = (float*)d_out;  // [mu (512*256), logstd (512*256)]

    float *p_prev, *p_i, *p_h1, *p_s2, *p_s3, *p_h2, *p_acc;
    cudaGetSymbolAddress((void**)&p_prev, g_prev);
    cudaGetSymbolAddress((void**)&p_i,    g_i);
    cudaGetSymbolAddress((void**)&p_h1,   g_h1);
    cudaGetSymbolAddress((void**)&p_s2,   g_s2);
    cudaGetSymbolAddress((void**)&p_s3,   g_s3);
    cudaGetSymbolAddress((void**)&p_h2,   g_h2);
    cudaGetSymbolAddress((void**)&p_acc,  g_acc);

    cudaFuncSetAttribute(k_nn_mma,
                         cudaFuncAttributeMaxDynamicSharedMemorySize, SM_TOTAL);

    // Stage 1: exact-quality nearest neighbor via bf16x3 mma.sync
    k_prep_codes<<<BDIM, CDIM>>>(codes);
    k_init_best<<<1, 512>>>();
    k_nn_mma<<<NBLK, 512, SM_TOTAL>>>(cb);
    k_gather<<<BDIM, CDIM>>>(cb);

    // Stage 2: MLP
    dim3 gH(HDIM / GBN, BDIM / GBM);   // (16, 8)
    dim3 gC(CDIM / GBN, BDIM / GBM);   // (4, 8)
    k_gemm<<<gH, 256>>>(p_prev, nullptr, w_in,  b_in,  p_i,   HDIM, CDIM, 0);
    k_gemm<<<gH, 256>>>(p_i,    nullptr, w_h1,  b_h1,  p_h1,  HDIM, HDIM, 0);
    k_gemm<<<gH, 256>>>(p_h1,   nullptr, w_s2,  b_s2,  p_s2,  HDIM, HDIM, 0);
    k_gemm<<<gH, 256>>>(p_h1,   nullptr, w_s3,  b_s3,  p_s3,  HDIM, HDIM, 0);
    k_gemm<<<gH, 256>>>(p_h1,   p_s2,    w_h2,  b_h2,  p_h2,  HDIM, HDIM, 0);
    k_gemm<<<gH, 256>>>(p_h1,   nullptr, w_s1o, b_s1o, p_acc, HDIM, HDIM, 0);
    k_gemm<<<gH, 256>>>(p_h2,   nullptr, w_s2o, b_s2o, p_acc, HDIM, HDIM, 1);
    k_gemm<<<gH, 256>>>(p_h2,   p_s3,    w_h3,  b_h3,  p_acc, HDIM, HDIM, 1);
    k_gemm<<<gC, 256>>>(p_acc,  nullptr, w_mu,  b_mu,  out,               CDIM, HDIM, 2);
    k_gemm<<<gC, 256>>>(p_acc,  nullptr, w_s,   b_s,   out + BDIM * CDIM, CDIM, HDIM, 2);
}

// round 16
// speedup vs baseline: 3.0451x; 1.3659x over previous
#include <cuda_runtime.h>
#include <cuda_bf16.h>
#include <cstdint>
#include <math.h>

// Problem dims (fixed by the dataset)
#define BDIM 512      // batch (codes)
#define CDIM 256      // feature dim
#define HDIM 1024     // hidden dim
#define NCB  500000   // codebook rows
#define NRG  3907     // row groups of 128
#define NBLK2 (NRG * 2)   // x2 code groups of 256

typedef unsigned long long u64;

// ---------------------------------------------------------------------------
// Device scratch (no allocations allowed)
// ---------------------------------------------------------------------------
__device__ u64 g_best[BDIM];
__device__ __align__(16) __nv_bfloat16 g_cA_hi[BDIM * CDIM];  // codes hi
__device__ __align__(16) __nv_bfloat16 g_cA_lo[BDIM * CDIM];  // codes lo
__device__ float g_prev[BDIM * CDIM];
__device__ float g_i  [BDIM * HDIM];
__device__ float g_h1 [BDIM * HDIM];
__device__ float g_s2 [BDIM * HDIM];
__device__ float g_s3 [BDIM * HDIM];
__device__ float g_h2 [BDIM * HDIM];
__device__ float g_acc[BDIM * HDIM];

// ---------------------------------------------------------------------------
// PTX helpers (baseline-family only: mma.sync / ldmatrix / cp.async)
// ---------------------------------------------------------------------------
__device__ __forceinline__ uint32_t smem_u32(const void* p) {
    uint32_t a;
    asm("{ .reg .u64 t; cvta.to.shared.u64 t, %1; cvt.u32.u64 %0, t; }"
        : "=r"(a) : "l"(p));
    return a;
}
__device__ __forceinline__ void ldsm4(uint32_t* r, uint32_t addr) {
    asm volatile("ldmatrix.sync.aligned.m8n8.x4.shared.b16 {%0,%1,%2,%3}, [%4];"
                 : "=r"(r[0]), "=r"(r[1]), "=r"(r[2]), "=r"(r[3]) : "r"(addr));
}
__device__ __forceinline__ void ldsm2(uint32_t* r, uint32_t addr) {
    asm volatile("ldmatrix.sync.aligned.m8n8.x2.shared.b16 {%0,%1}, [%2];"
                 : "=r"(r[0]), "=r"(r[1]) : "r"(addr));
}
__device__ __forceinline__ void mma_bf16(float* d, const uint32_t* a,
                                         const uint32_t* b) {
    asm volatile(
        "mma.sync.aligned.m16n8k16.row.col.f32.bf16.bf16.f32 "
        "{%0,%1,%2,%3}, {%4,%5,%6,%7}, {%8,%9}, {%0,%1,%2,%3};"
        : "+f"(d[0]), "+f"(d[1]), "+f"(d[2]), "+f"(d[3])
        : "r"(a[0]), "r"(a[1]), "r"(a[2]), "r"(a[3]), "r"(b[0]), "r"(b[1]));
}
__device__ __forceinline__ void cp16(uint32_t dst, const void* src) {
    asm volatile("cp.async.cg.shared.global [%0], [%1], 16;"
                 :: "r"(dst), "l"(src));
}
__device__ __forceinline__ void cp_commit_wait() {
    asm volatile("cp.async.commit_group;");
    asm volatile("cp.async.wait_group 0;");
}

__device__ __forceinline__ uint32_t split2(float x, float y, uint32_t& lo) {
    __nv_bfloat16 hx = __float2bfloat16_rn(x);
    __nv_bfloat16 hy = __float2bfloat16_rn(y);
    __nv_bfloat16 lx = __float2bfloat16_rn(x - __bfloat162float(hx));
    __nv_bfloat16 ly = __float2bfloat16_rn(y - __bfloat162float(hy));
    __nv_bfloat162 hh; hh.x = hx; hh.y = hy;
    __nv_bfloat162 ll; ll.x = lx; ll.y = ly;
    lo = *(uint32_t*)&ll;
    return *(uint32_t*)&hh;
}

__device__ __forceinline__ u64 dist_key(float dot, float nr, unsigned n) {
    float dist = fmaf(-2.f, dot, nr);
    unsigned kb = __float_as_uint(dist);
    kb ^= (kb & 0x80000000u) ? 0xFFFFFFFFu : 0x80000000u;
    return ((u64)kb << 32) | n;
}

// ---------------------------------------------------------------------------
// Setup kernels
// ---------------------------------------------------------------------------
__global__ void k_init_best() {
    g_best[threadIdx.x] = 0xFFFFFFFFFFFFFFFFull;
}

// codes -> plain [512][256] bf16 hi/lo images
__global__ void k_prep_codes(const float* __restrict__ codes) {
    int m = blockIdx.x, k = threadIdx.x;
    float x = codes[m * CDIM + k];
    __nv_bfloat16 h = __float2bfloat16_rn(x);
    __nv_bfloat16 l = __float2bfloat16_rn(x - __bfloat162float(h));
    g_cA_hi[m * CDIM + k] = h;
    g_cA_lo[m * CDIM + k] = l;
}

// ---------------------------------------------------------------------------
// NN argmin: bf16x3 via mma.sync.m16n8k16
// Block: 256 codes (code-group cg) x 128 rows (row-group rg), K=256 in 4
// chunks of 64. 512 threads, 16 warps: warp tile 64 codes x 32 rows.
// Grid ordered cg-fast so both cg blocks of one rg share L2 codebook lines.
// ---------------------------------------------------------------------------
#define KSTR    144                    // 128B row + 16B pad
#define OFF_AHI 0
#define OFF_ALO (256 * KSTR)           // 36864
#define OFF_BHI (2 * 256 * KSTR)       // 73728
#define OFF_BLO (OFF_BHI + 128 * KSTR) // 92160
#define OFF_NRM (OFF_BLO + 128 * KSTR) // 110592
#define SM_NN   (OFF_NRM + 128 * 4)    // 111104

__global__ __launch_bounds__(512, 1)
void k_nn_mma(const float* __restrict__ cb) {
    extern __shared__ char smem[];
    const uint32_t sb = smem_u32(smem);
    const int tid  = threadIdx.x;
    const int wid  = tid >> 5;
    const int lane = tid & 31;
    const int mg   = wid & 3;    // code group in block (64 codes)
    const int ng   = wid >> 2;   // row group in block (32 rows)
    const int cg   = blockIdx.x & 1;        // 256-code group
    const int rg   = blockIdx.x >> 1;       // 128-row group
    const int n0   = rg * 128;

    // B-load role: thread owns row r, 16 k-cols at q*16
    const int r = tid >> 2;      // 0..127
    const int q = tid & 3;       // 0..3
    const int grow = min(n0 + r, NCB - 1);
    const float4* bsrc = (const float4*)(cb + (size_t)grow * CDIM);

    // ldmatrix base addresses
    const uint32_t aHiRow = sb + OFF_AHI + (mg * 64 + (lane & 15)) * KSTR +
                            ((lane >> 4) << 4);
    const uint32_t aLoRow = aHiRow + (OFF_ALO - OFF_AHI);
    const uint32_t bHiRow = sb + OFF_BHI + (ng * 32 + (lane & 7)) * KSTR +
                            (((lane >> 3) & 1) << 4);
    const uint32_t bLoRow = bHiRow + (OFF_BLO - OFF_BHI);

    float acc[4][4][4];
    #pragma unroll
    for (int a = 0; a < 4; a++)
        #pragma unroll
        for (int b = 0; b < 4; b++)
            #pragma unroll
            for (int e = 0; e < 4; e++) acc[a][b][e] = 0.f;
    float sq = 0.f;

    const char* aHiG = (const char*)g_cA_hi;
    const char* aLoG = (const char*)g_cA_lo;

    // Prefetch B registers for chunk 0 (cols q*16 .. q*16+15)
    float4 v[4];
    #pragma unroll
    for (int t = 0; t < 4; t++) v[t] = bsrc[q * 4 + t];

    for (int c = 0; c < 4; c++) {
        __syncthreads();   // previous chunk's mma reads done

        // --- A: cp.async codes chunk (hi+lo), 8 pieces/thread ---
        #pragma unroll
        for (int j = 0; j < 4; j++) {
            int lin = j * 512 + tid;        // 0..2047
            int row = lin >> 3;
            int qq  = lin & 7;
            uint32_t d = sb + OFF_AHI + row * KSTR + qq * 16;
            const char* s = aHiG + (size_t)(cg * 256 + row) * 512 + c * 128 + qq * 16;
            cp16(d, s);
            cp16(d + (OFF_ALO - OFF_AHI), s + (aLoG - aHiG));
        }

        // --- B: split prefetched regs, STS; exact fp32 norms ---
        #pragma unroll
        for (int t = 0; t < 2; t++) {
            float4 va = v[2 * t], vb = v[2 * t + 1];
            sq = fmaf(va.x, va.x, sq); sq = fmaf(va.y, va.y, sq);
            sq = fmaf(va.z, va.z, sq); sq = fmaf(va.w, va.w, sq);
            sq = fmaf(vb.x, vb.x, sq); sq = fmaf(vb.y, vb.y, sq);
            sq = fmaf(vb.z, vb.z, sq); sq = fmaf(vb.w, vb.w, sq);
            uint4 h, l;
            h.x = split2(va.x, va.y, l.x);
            h.y = split2(va.z, va.w, l.y);
            h.z = split2(vb.x, vb.y, l.z);
            h.w = split2(vb.z, vb.w, l.w);
            *(uint4*)(smem + OFF_BHI + r * KSTR + q * 32 + t * 16) = h;
            *(uint4*)(smem + OFF_BLO + r * KSTR + q * 32 + t * 16) = l;
        }
        // Prefetch next chunk's B (latency hides under MMA below)
        if (c < 3) {
            #pragma unroll
            for (int t = 0; t < 4; t++) v[t] = bsrc[(c + 1) * 16 + q * 4 + t];
        }

        cp_commit_wait();
        __syncthreads();

        // --- MMA: 4 k16 steps x 4 mtiles x 4 ntiles x 3 terms ---
        #pragma unroll
        for (int s = 0; s < 4; s++) {
            uint32_t bh[4][2], bl[4][2];
            #pragma unroll
            for (int nt = 0; nt < 4; nt++) {
                ldsm2(bh[nt], bHiRow + nt * 8 * KSTR + s * 32);
                ldsm2(bl[nt], bLoRow + nt * 8 * KSTR + s * 32);
            }
            #pragma unroll
            for (int mt = 0; mt < 4; mt++) {
                uint32_t af[4];
                ldsm4(af, aHiRow + mt * 16 * KSTR + s * 32);
                #pragma unroll
                for (int nt = 0; nt < 4; nt++) mma_bf16(acc[mt][nt], af, bh[nt]);
                #pragma unroll
                for (int nt = 0; nt < 4; nt++) mma_bf16(acc[mt][nt], af, bl[nt]);
                ldsm4(af, aLoRow + mt * 16 * KSTR + s * 32);
                #pragma unroll
                for (int nt = 0; nt < 4; nt++) mma_bf16(acc[mt][nt], af, bh[nt]);
            }
        }
    }

    // Row norms: reduce over the 4 lanes sharing a row, publish to smem
    sq += __shfl_xor_sync(0xFFFFFFFFu, sq, 1);
    sq += __shfl_xor_sync(0xFFFFFFFFu, sq, 2);
    float* nrm = (float*)(smem + OFF_NRM);
    if ((tid & 3) == 0) nrm[r] = sq;
    __syncthreads();

    // Epilogue: dist = nrm - 2*dot; packed-key argmin
    const int g = lane >> 2;
    const int i = lane & 3;
    #pragma unroll
    for (int mt = 0; mt < 4; mt++) {
        u64 b0 = 0xFFFFFFFFFFFFFFFFull;   // code row g
        u64 b1 = 0xFFFFFFFFFFFFFFFFull;   // code row g+8
        #pragma unroll
        for (int nt = 0; nt < 4; nt++) {
            int nl = ng * 32 + nt * 8 + 2 * i;
            int n  = n0 + nl;
            const float* d = acc[mt][nt];
            if (n < NCB) {
                u64 e = dist_key(d[0], nrm[nl], (unsigned)n);
                if (e < b0) b0 = e;
                e = dist_key(d[2], nrm[nl], (unsigned)n);
                if (e < b1) b1 = e;
            }
            if (n + 1 < NCB) {
                u64 e = dist_key(d[1], nrm[nl + 1], (unsigned)(n + 1));
                if (e < b0) b0 = e;
                e = dist_key(d[3], nrm[nl + 1], (unsigned)(n + 1));
                if (e < b1) b1 = e;
            }
        }
        #pragma unroll
        for (int m = 1; m <= 2; m++) {
            u64 o0 = __shfl_xor_sync(0xFFFFFFFFu, b0, m);
            u64 o1 = __shfl_xor_sync(0xFFFFFFFFu, b1, m);
            if (o0 < b0) b0 = o0;
            if (o1 < b1) b1 = o1;
        }
        if (i == 0) {
            int code = cg * 256 + mg * 64 + mt * 16 + g;
            atomicMin(&g_best[code], b0);
            atomicMin(&g_best[code + 8], b1);
        }
    }
}

// prev[m,:] = codebook[best_idx[m], :]
__global__ void k_gather(const float* __restrict__ cb) {
    int m = blockIdx.x;
    unsigned idx = (unsigned)(g_best[m] & 0xFFFFFFFFull);
    g_prev[(size_t)m * CDIM + threadIdx.x] =
        cb[(size_t)idx * CDIM + threadIdx.x];
}

// ---------------------------------------------------------------------------
// MLP GEMM on tensor cores: Y(op) = act( (X [+X2]) @ W^T + bias )
// bf16x3 hi/lo split of both operands, fp32 accumulate.
// Block tile 64x64, k-chunk 64, 256 threads (8 warps, warp tile 32x16).
// mode 0: Y = tanh(r);  mode 1: Y += tanh(r);  mode 2: Y = r
// ---------------------------------------------------------------------------
#define GXH 0
#define GXL 9216
#define GWH 18432
#define GWL 27648

__global__ __launch_bounds__(256)
void k_gemm_mma(const float* __restrict__ X, const float* __restrict__ X2,
                const float* __restrict__ W, const float* __restrict__ bias,
                float* __restrict__ Y, int Nv, int Kv, int mode) {
    __shared__ __align__(16) char smg[4 * 9216];
    const uint32_t sb = smem_u32(smg);
    const int tid  = threadIdx.x;
    const int wid  = tid >> 5;
    const int lane = tid & 31;
    const int mg   = wid & 1;    // 2 groups of 32 rows
    const int ng   = wid >> 1;   // 4 groups of 16 cols
    const int m0   = blockIdx.y * 64;
    const int n0   = blockIdx.x * 64;

    const uint32_t aHiRow = sb + GXH + (mg * 32 + (lane & 15)) * KSTR +
                            ((lane >> 4) << 4);
    const uint32_t aLoRow = aHiRow + (GXL - GXH);
    const uint32_t bHiRow = sb + GWH + (ng * 16 + (lane & 7)) * KSTR +
                            (((lane >> 3) & 1) << 4);
    const uint32_t bLoRow = bHiRow + (GWL - GWH);

    float acc[2][2][4];
    #pragma unroll
    for (int a = 0; a < 2; a++)
        #pragma unroll
        for (int b = 0; b < 2; b++)
            #pragma unroll
            for (int e = 0; e < 4; e++) acc[a][b][e] = 0.f;

    // Loader role: 1024 float4 slots per matrix, 4 per thread
    const int nchunks = Kv >> 6;
    float4 xv[4], wv[4];
    #pragma unroll
    for (int j = 0; j < 4; j++) {
        int lin = j * 256 + tid;
        int row = lin >> 4, c4 = lin & 15;
        xv[j] = *(const float4*)&X[(size_t)(m0 + row) * Kv + c4 * 4];
        if (X2) {
            float4 t = *(const float4*)&X2[(size_t)(m0 + row) * Kv + c4 * 4];
            xv[j].x += t.x; xv[j].y += t.y; xv[j].z += t.z; xv[j].w += t.w;
        }
        wv[j] = *(const float4*)&W[(size_t)(n0 + row) * Kv + c4 * 4];
    }

    for (int c = 0; c < nchunks; c++) {
        __syncthreads();

        #pragma unroll
        for (int j = 0; j < 4; j++) {
            int lin = j * 256 + tid;
            int row = lin >> 4, c4 = lin & 15;
            uint2 h, l;
            h.x = split2(xv[j].x, xv[j].y, l.x);
            h.y = split2(xv[j].z, xv[j].w, l.y);
            *(uint2*)(smg + GXH + row * KSTR + c4 * 8) = h;
            *(uint2*)(smg + GXL + row * KSTR + c4 * 8) = l;
            h.x = split2(wv[j].x, wv[j].y, l.x);
            h.y = split2(wv[j].z, wv[j].w, l.y);
            *(uint2*)(smg + GWH + row * KSTR + c4 * 8) = h;
            *(uint2*)(smg + GWL + row * KSTR + c4 * 8) = l;
        }
        if (c + 1 < nchunks) {
            int k0 = (c + 1) * 64;
            #pragma unroll
            for (int j = 0; j < 4; j++) {
                int lin = j * 256 + tid;
                int row = lin >> 4, c4 = lin & 15;
                xv[j] = *(const float4*)&X[(size_t)(m0 + row) * Kv + k0 + c4 * 4];
                if (X2) {
                    float4 t = *(const float4*)&X2[(size_t)(m0 + row) * Kv + k0 + c4 * 4];
                    xv[j].x += t.x; xv[j].y += t.y; xv[j].z += t.z; xv[j].w += t.w;
                }
                wv[j] = *(const float4*)&W[(size_t)(n0 + row) * Kv + k0 + c4 * 4];
            }
        }
        __syncthreads();

        #pragma unroll
        for (int s = 0; s < 4; s++) {
            uint32_t bh[2][2], bl[2][2];
            #pragma unroll
            for (int nt = 0; nt < 2; nt++) {
                ldsm2(bh[nt], bHiRow + nt * 8 * KSTR + s * 32);
                ldsm2(bl[nt], bLoRow + nt * 8 * KSTR + s * 32);
            }
            #pragma unroll
            for (int mt = 0; mt < 2; mt++) {
                uint32_t af[4];
                ldsm4(af, aHiRow + mt * 16 * KSTR + s * 32);
                #pragma unroll
                for (int nt = 0; nt < 2; nt++) mma_bf16(acc[mt][nt], af, bh[nt]);
                #pragma unroll
                for (int nt = 0; nt < 2; nt++) mma_bf16(acc[mt][nt], af, bl[nt]);
                ldsm4(af, aLoRow + mt * 16 * KSTR + s * 32);
                #pragma unroll
                for (int nt = 0; nt < 2; nt++) mma_bf16(acc[mt][nt], af, bh[nt]);
            }
        }
    }

    // Epilogue
    const int g = lane >> 2;
    const int i = lane & 3;
    #pragma unroll
    for (int mt = 0; mt < 2; mt++) {
        #pragma unroll
        for (int nt = 0; nt < 2; nt++) {
            const float* d = acc[mt][nt];
            int n = n0 + ng * 16 + nt * 8 + 2 * i;
            float bia0 = bias[n], bia1 = bias[n + 1];
            #pragma unroll
            for (int e = 0; e < 4; e++) {
                int m  = m0 + mg * 32 + mt * 16 + g + (e >> 1) * 8;
                int nn = n + (e & 1);
                float v = d[e] + ((e & 1) ? bia1 : bia0);
                if (mode != 2) v = tanhf(v);
                size_t o = (size_t)m * Nv + nn;
                if (mode == 1) Y[o] += v;
                else           Y[o] = v;
            }
        }
    }
}

// ---------------------------------------------------------------------------
// Launch
// ---------------------------------------------------------------------------
extern "C" void kernel_launch(void* const* d_in, const int* in_sizes, int n_in,
                              void* d_out, int out_size) {
    const float* codes = (const float*)d_in[0];
    const float* cb    = (const float*)d_in[1];
    const float* w_in  = (const float*)d_in[2];
    const float* b_in  = (const float*)d_in[3];
    const float* w_h1  = (const float*)d_in[4];
    const float* b_h1  = (const float*)d_in[5];
    const float* w_s2  = (const float*)d_in[6];
    const float* b_s2  = (const float*)d_in[7];
    const float* w_s3  = (const float*)d_in[8];
    const float* b_s3  = (const float*)d_in[9];
    const float* w_h2  = (const float*)d_in[10];
    const float* b_h2  = (const float*)d_in[11];
    const float* w_s1o = (const float*)d_in[12];
    const float* b_s1o = (const float*)d_in[13];
    const float* w_s2o = (const float*)d_in[14];
    const float* b_s2o = (const float*)d_in[15];
    const float* w_h3  = (const float*)d_in[16];
    const float* b_h3  = (const float*)d_in[17];
    const float* w_mu  = (const float*)d_in[18];
    const float* b_mu  = (const float*)d_in[19];
    const float* w_s   = (const float*)d_in[20];
    const float* b_s   = (const float*)d_in[21];
    float* out = (float*)d_out;  // [mu (512*256), logstd (512*256)]

    float *p_prev, *p_i, *p_h1, *p_s2, *p_s3, *p_h2, *p_acc;
    cudaGetSymbolAddress((void**)&p_prev, g_prev);
    cudaGetSymbolAddress((void**)&p_i,    g_i);
    cudaGetSymbolAddress((void**)&p_h1,   g_h1);
    cudaGetSymbolAddress((void**)&p_s2,   g_s2);
    cudaGetSymbolAddress((void**)&p_s3,   g_s3);
    cudaGetSymbolAddress((void**)&p_h2,   g_h2);
    cudaGetSymbolAddress((void**)&p_acc,  g_acc);

    cudaFuncSetAttribute(k_nn_mma,
                         cudaFuncAttributeMaxDynamicSharedMemorySize, SM_NN);

    // Stage 1: exact-quality nearest neighbor via bf16x3 mma.sync
    k_prep_codes<<<BDIM, CDIM>>>(codes);
    k_init_best<<<1, 512>>>();
    k_nn_mma<<<NBLK2, 512, SM_NN>>>(cb);
    k_gather<<<BDIM, CDIM>>>(cb);

    // Stage 2: MLP on tensor cores
    dim3 gH(HDIM / 64, BDIM / 64);   // (16, 8)
    dim3 gC(CDIM / 64, BDIM / 64);   // (4, 8)
    k_gemm_mma<<<gH, 256>>>(p_prev, nullptr, w_in,  b_in,  p_i,   HDIM, CDIM, 0);
    k_gemm_mma<<<gH, 256>>>(p_i,    nullptr, w_h1,  b_h1,  p_h1,  HDIM, HDIM, 0);
    k_gemm_mma<<<gH, 256>>>(p_h1,   nullptr, w_s2,  b_s2,  p_s2,  HDIM, HDIM, 0);
    k_gemm_mma<<<gH, 256>>>(p_h1,   nullptr, w_s3,  b_s3,  p_s3,  HDIM, HDIM, 0);
    k_gemm_mma<<<gH, 256>>>(p_h1,   p_s2,    w_h2,  b_h2,  p_h2,  HDIM, HDIM, 0);
    k_gemm_mma<<<gH, 256>>>(p_h1,   nullptr, w_s1o, b_s1o, p_acc, HDIM, HDIM, 0);
    k_gemm_mma<<<gH, 256>>>(p_h2,   nullptr, w_s2o, b_s2o, p_acc, HDIM, HDIM, 1);
    k_gemm_mma<<<gH, 256>>>(p_h2,   p_s3,    w_h3,  b_h3,  p_acc, HDIM, HDIM, 1);
    k_gemm_mma<<<gC, 256>>>(p_acc,  nullptr, w_mu,  b_mu,  out,               CDIM, HDIM, 2);
    k_gemm_mma<<<gC, 256>>>(p_acc,  nullptr, w_s,   b_s,   out + BDIM * CDIM, CDIM, HDIM, 2);
}

// round 17
// speedup vs baseline: 3.2613x; 1.0710x over previous
#include <cuda_runtime.h>
#include <cuda_bf16.h>
#include <cstdint>
#include <math.h>

// Problem dims (fixed by the dataset)
#define BDIM 512      // batch (codes)
#define CDIM 256      // feature dim
#define HDIM 1024     // hidden dim
#define NCB  500000   // codebook rows
#define NRG  3907     // row groups of 128 (last partial)
#define NSLICE 148
#define RGPB 27       // ceil(3907/148) row-groups per block slice

typedef unsigned long long u64;

// ---------------------------------------------------------------------------
// Device scratch (no allocations allowed)
// ---------------------------------------------------------------------------
__device__ u64 g_best[BDIM];
__device__ __align__(16) __nv_bfloat16 g_cA_hi[BDIM * CDIM];  // codes hi
__device__ __align__(16) __nv_bfloat16 g_cA_lo[BDIM * CDIM];  // codes lo
__device__ float g_prev[BDIM * CDIM];
__device__ float g_i  [BDIM * HDIM];
__device__ float g_h1 [BDIM * HDIM];
__device__ float g_s2 [BDIM * HDIM];
__device__ float g_s3 [BDIM * HDIM];
__device__ float g_h2 [BDIM * HDIM];
__device__ float g_acc[BDIM * HDIM];

// ---------------------------------------------------------------------------
// PTX helpers (baseline-family only: mma.sync / ldmatrix / cp.async)
// ---------------------------------------------------------------------------
__device__ __forceinline__ uint32_t smem_u32(const void* p) {
    uint32_t a;
    asm("{ .reg .u64 t; cvta.to.shared.u64 t, %1; cvt.u32.u64 %0, t; }"
        : "=r"(a) : "l"(p));
    return a;
}
__device__ __forceinline__ void ldsm4(uint32_t* r, uint32_t addr) {
    asm volatile("ldmatrix.sync.aligned.m8n8.x4.shared.b16 {%0,%1,%2,%3}, [%4];"
                 : "=r"(r[0]), "=r"(r[1]), "=r"(r[2]), "=r"(r[3]) : "r"(addr));
}
__device__ __forceinline__ void ldsm2(uint32_t* r, uint32_t addr) {
    asm volatile("ldmatrix.sync.aligned.m8n8.x2.shared.b16 {%0,%1}, [%2];"
                 : "=r"(r[0]), "=r"(r[1]) : "r"(addr));
}
__device__ __forceinline__ void mma_bf16(float* d, const uint32_t* a,
                                         const uint32_t* b) {
    asm volatile(
        "mma.sync.aligned.m16n8k16.row.col.f32.bf16.bf16.f32 "
        "{%0,%1,%2,%3}, {%4,%5,%6,%7}, {%8,%9}, {%0,%1,%2,%3};"
        : "+f"(d[0]), "+f"(d[1]), "+f"(d[2]), "+f"(d[3])
        : "r"(a[0]), "r"(a[1]), "r"(a[2]), "r"(a[3]), "r"(b[0]), "r"(b[1]));
}
__device__ __forceinline__ void cp16(uint32_t dst, const void* src) {
    asm volatile("cp.async.cg.shared.global [%0], [%1], 16;"
                 :: "r"(dst), "l"(src));
}
__device__ __forceinline__ void cp_commit_wait() {
    asm volatile("cp.async.commit_group;");
    asm volatile("cp.async.wait_group 0;");
}

__device__ __forceinline__ uint32_t split2(float x, float y, uint32_t& lo) {
    __nv_bfloat16 hx = __float2bfloat16_rn(x);
    __nv_bfloat16 hy = __float2bfloat16_rn(y);
    __nv_bfloat16 lx = __float2bfloat16_rn(x - __bfloat162float(hx));
    __nv_bfloat16 ly = __float2bfloat16_rn(y - __bfloat162float(hy));
    __nv_bfloat162 hh; hh.x = hx; hh.y = hy;
    __nv_bfloat162 ll; ll.x = lx; ll.y = ly;
    lo = *(uint32_t*)&ll;
    return *(uint32_t*)&hh;
}

__device__ __forceinline__ u64 dist_key(float dot, float nr, unsigned n) {
    float dist = fmaf(-2.f, dot, nr);
    unsigned kb = __float_as_uint(dist);
    kb ^= (kb & 0x80000000u) ? 0xFFFFFFFFu : 0x80000000u;
    return ((u64)kb << 32) | n;
}

// ---------------------------------------------------------------------------
// Setup kernels
// ---------------------------------------------------------------------------
__global__ void k_init_best() {
    g_best[threadIdx.x] = 0xFFFFFFFFFFFFFFFFull;
}

// codes -> plain [512][256] bf16 hi/lo images
__global__ void k_prep_codes(const float* __restrict__ codes) {
    int m = blockIdx.x, k = threadIdx.x;
    float x = codes[m * CDIM + k];
    __nv_bfloat16 h = __float2bfloat16_rn(x);
    __nv_bfloat16 l = __float2bfloat16_rn(x - __bfloat162float(h));
    g_cA_hi[m * CDIM + k] = h;
    g_cA_lo[m * CDIM + k] = l;
}

// ---------------------------------------------------------------------------
// NN argmin: bf16x3 via mma.sync.m16n8k16, persistent A-resident blocks.
// Block = 128 codes (cg) x full K=256 in smem; iterates 27 row-groups of 128.
// B double-buffered in k-chunks of 64; pipeline LDG(t+2)/MMA(t)/STS(t+1).
// Grid 148 slices x 4 cg, cg-fast so concurrent blocks share codebook L2.
// 512 threads, 16 warps: warp tile 32 codes x 32 rows.
// ---------------------------------------------------------------------------
#define KSTR     144                       // 128B row + 16B pad
#define ACH      18432                     // one A chunk (128 rows x KSTR)
#define OFF_AHI  0                         // 4 chunks  -> 73728
#define OFF_ALO  73728                     // 4 chunks  -> 147456
#define OFF_B    147456                    // 2 bufs x (hi 18432 + lo 18432)
#define BBUF     36864
#define OFF_NRM  (OFF_B + 2 * BBUF)        // 221184
#define SM_NN    (OFF_NRM + 128 * 4)       // 221696

__global__ __launch_bounds__(512, 1)
void k_nn_mma(const float* __restrict__ cb) {
    extern __shared__ char smem[];
    const uint32_t sb = smem_u32(smem);
    const int tid  = threadIdx.x;
    const int wid  = tid >> 5;
    const int lane = tid & 31;
    const int mg   = wid & 3;    // 4 groups of 32 codes
    const int ng   = wid >> 2;   // 4 groups of 32 rows
    const int cg   = blockIdx.x & 3;        // 128-code group
    const int slice = blockIdx.x >> 2;
    const int rg0  = slice * RGPB;
    const int nrg  = min(RGPB, NRG - rg0);
    if (nrg <= 0) return;
    const int T = nrg * 4;       // pipeline steps (k-chunks)

    // B-load role: thread owns local row rr, 16 k-cols at q*16
    const int r16 = tid >> 2;    // 0..127 local row
    const int q   = tid & 3;     // 0..3

    // ldmatrix base addresses (chunk offset added per step)
    const uint32_t aHiRow = sb + OFF_AHI + (mg * 32 + (lane & 15)) * KSTR +
                            ((lane >> 4) << 4);
    const uint32_t aLoRow = aHiRow + (OFF_ALO - OFF_AHI);
    const uint32_t bRowBase = (ng * 32 + (lane & 7)) * KSTR +
                              (((lane >> 3) & 1) << 4);

    // ---- load A once: 128 codes x K=256, hi+lo, chunk-major ----
    {
        const char* aHiG = (const char*)g_cA_hi;
        const char* aLoG = (const char*)g_cA_lo;
        #pragma unroll
        for (int j = 0; j < 8; j++) {
            int lin = j * 512 + tid;          // 0..4095
            int row = lin >> 5;
            int rem = lin & 31;
            int c   = rem >> 3;
            int q8  = rem & 7;
            uint32_t d = sb + OFF_AHI + c * ACH + row * KSTR + q8 * 16;
            size_t s = (size_t)(cg * 128 + row) * 512 + c * 128 + q8 * 16;
            cp16(d, aHiG + s);
            cp16(d + (OFF_ALO - OFF_AHI), aLoG + s);
        }
    }

    float acc[2][4][4];
    #pragma unroll
    for (int a = 0; a < 2; a++)
        #pragma unroll
        for (int b = 0; b < 4; b++)
            #pragma unroll
            for (int e = 0; e < 4; e++) acc[a][b][e] = 0.f;
    u64 best[2][2];
    best[0][0] = best[0][1] = best[1][0] = best[1][1] = 0xFFFFFFFFFFFFFFFFull;
    float sq = 0.f;
    float* nrm = (float*)(smem + OFF_NRM);

    // B LDG helper data
    float4 v[4], vn[4];
    // prolog: step 0 load + split into buf0; step 1 load
    {
        int grow = min(rg0 * 128 + r16, NCB - 1);
        const float4* p = (const float4*)(cb + (size_t)grow * CDIM) + q * 4;
        #pragma unroll
        for (int k = 0; k < 4; k++) v[k] = p[k];
        // split step 0 -> buf 0
        #pragma unroll
        for (int t2 = 0; t2 < 2; t2++) {
            float4 va = v[2 * t2], vb = v[2 * t2 + 1];
            sq = fmaf(va.x, va.x, sq); sq = fmaf(va.y, va.y, sq);
            sq = fmaf(va.z, va.z, sq); sq = fmaf(va.w, va.w, sq);
            sq = fmaf(vb.x, vb.x, sq); sq = fmaf(vb.y, vb.y, sq);
            sq = fmaf(vb.z, vb.z, sq); sq = fmaf(vb.w, vb.w, sq);
            uint4 h, l;
            h.x = split2(va.x, va.y, l.x);
            h.y = split2(va.z, va.w, l.y);
            h.z = split2(vb.x, vb.y, l.z);
            h.w = split2(vb.z, vb.w, l.w);
            *(uint4*)(smem + OFF_B + r16 * KSTR + q * 32 + t2 * 16) = h;
            *(uint4*)(smem + OFF_B + 18432 + r16 * KSTR + q * 32 + t2 * 16) = l;
        }
        // load step 1 (chunk 1 of rg0)
        if (T > 1) {
            const float4* p1 = (const float4*)(cb + (size_t)grow * CDIM) + 16 + q * 4;
            #pragma unroll
            for (int k = 0; k < 4; k++) v[k] = p1[k];
        }
        cp_commit_wait();   // A resident
        __syncthreads();
    }

    for (int t = 0; t < T; t++) {
        const int c = t & 3;
        const int bufc = (t & 1) ? OFF_B + BBUF : OFF_B;

        // 1. finalize norms for current rg (all splits for it are done)
        if (c == 3) {
            float s2 = sq;
            s2 += __shfl_xor_sync(0xFFFFFFFFu, s2, 1);
            s2 += __shfl_xor_sync(0xFFFFFFFFu, s2, 2);
            if ((tid & 3) == 0) nrm[r16] = s2;
            sq = 0.f;
        }

        // 2. prefetch LDG for step t+2
        if (t + 2 < T) {
            int s = t + 2;
            int grow = min((rg0 + (s >> 2)) * 128 + r16, NCB - 1);
            const float4* p = (const float4*)(cb + (size_t)grow * CDIM) +
                              (s & 3) * 16 + q * 4;
            #pragma unroll
            for (int k = 0; k < 4; k++) vn[k] = p[k];
        }

        // 3. MMA step t: A chunk c, B buf (t&1)
        {
            const uint32_t aH = aHiRow + c * ACH;
            const uint32_t aL = aLoRow + c * ACH;
            const uint32_t bH = sb + bufc + bRowBase;
            const uint32_t bL = bH + 18432;
            #pragma unroll
            for (int s = 0; s < 4; s++) {
                uint32_t bh[4][2], bl[4][2];
                #pragma unroll
                for (int nt = 0; nt < 4; nt++) {
                    ldsm2(bh[nt], bH + nt * 8 * KSTR + s * 32);
                    ldsm2(bl[nt], bL + nt * 8 * KSTR + s * 32);
                }
                #pragma unroll
                for (int mt = 0; mt < 2; mt++) {
                    uint32_t af[4];
                    ldsm4(af, aH + mt * 16 * KSTR + s * 32);
                    #pragma unroll
                    for (int nt = 0; nt < 4; nt++) mma_bf16(acc[mt][nt], af, bh[nt]);
                    #pragma unroll
                    for (int nt = 0; nt < 4; nt++) mma_bf16(acc[mt][nt], af, bl[nt]);
                    ldsm4(af, aL + mt * 16 * KSTR + s * 32);
                    #pragma unroll
                    for (int nt = 0; nt < 4; nt++) mma_bf16(acc[mt][nt], af, bh[nt]);
                }
            }
        }

        // 4. split step t+1 into the other buffer
        if (t + 1 < T) {
            const int bufn = (t & 1) ? OFF_B : OFF_B + BBUF;
            #pragma unroll
            for (int t2 = 0; t2 < 2; t2++) {
                float4 va = v[2 * t2], vb = v[2 * t2 + 1];
                sq = fmaf(va.x, va.x, sq); sq = fmaf(va.y, va.y, sq);
                sq = fmaf(va.z, va.z, sq); sq = fmaf(va.w, va.w, sq);
                sq = fmaf(vb.x, vb.x, sq); sq = fmaf(vb.y, vb.y, sq);
                sq = fmaf(vb.z, vb.z, sq); sq = fmaf(vb.w, vb.w, sq);
                uint4 h, l;
                h.x = split2(va.x, va.y, l.x);
                h.y = split2(va.z, va.w, l.y);
                h.z = split2(vb.x, vb.y, l.z);
                h.w = split2(vb.z, vb.w, l.w);
                *(uint4*)(smem + bufn + r16 * KSTR + q * 32 + t2 * 16) = h;
                *(uint4*)(smem + bufn + 18432 + r16 * KSTR + q * 32 + t2 * 16) = l;
            }
        }

        __syncthreads();

        // 6. epilogue at rg end: update per-thread running bests, reset acc
        if (c == 3) {
            const int n0 = (rg0 + (t >> 2)) * 128;
            const int g = lane >> 2;
            const int i = lane & 3;
            #pragma unroll
            for (int mt = 0; mt < 2; mt++) {
                #pragma unroll
                for (int nt = 0; nt < 4; nt++) {
                    int nl = ng * 32 + nt * 8 + 2 * i;
                    int n  = n0 + nl;
                    float* d = acc[mt][nt];
                    if (n < NCB) {
                        u64 e = dist_key(d[0], nrm[nl], (unsigned)n);
                        if (e < best[mt][0]) best[mt][0] = e;
                        e = dist_key(d[2], nrm[nl], (unsigned)n);
                        if (e < best[mt][1]) best[mt][1] = e;
                    }
                    if (n + 1 < NCB) {
                        u64 e = dist_key(d[1], nrm[nl + 1], (unsigned)(n + 1));
                        if (e < best[mt][0]) best[mt][0] = e;
                        e = dist_key(d[3], nrm[nl + 1], (unsigned)(n + 1));
                        if (e < best[mt][1]) best[mt][1] = e;
                    }
                    d[0] = d[1] = d[2] = d[3] = 0.f;
                }
            }
        }

        // 7. rotate prefetched regs
        #pragma unroll
        for (int k = 0; k < 4; k++) v[k] = vn[k];
    }

    // Final reduce across the 4 n-lanes sharing a code, then global atomicMin
    const int g = lane >> 2;
    #pragma unroll
    for (int mt = 0; mt < 2; mt++) {
        u64 b0 = best[mt][0], b1 = best[mt][1];
        #pragma unroll
        for (int m = 1; m <= 2; m++) {
            u64 o0 = __shfl_xor_sync(0xFFFFFFFFu, b0, m);
            u64 o1 = __shfl_xor_sync(0xFFFFFFFFu, b1, m);
            if (o0 < b0) b0 = o0;
            if (o1 < b1) b1 = o1;
        }
        if ((lane & 3) == 0) {
            int code = cg * 128 + mg * 32 + mt * 16 + g;
            atomicMin(&g_best[code], b0);
            atomicMin(&g_best[code + 8], b1);
        }
    }
}

// prev[m,:] = codebook[best_idx[m], :]
__global__ void k_gather(const float* __restrict__ cb) {
    int m = blockIdx.x;
    unsigned idx = (unsigned)(g_best[m] & 0xFFFFFFFFull);
    g_prev[(size_t)m * CDIM + threadIdx.x] =
        cb[(size_t)idx * CDIM + threadIdx.x];
}

// ---------------------------------------------------------------------------
// MLP GEMM on tensor cores: Y(op) = act( (X [+X2]) @ W^T + bias )
// bf16x3 hi/lo split of both operands, fp32 accumulate.
// Block tile 64x64, k-chunk 64, 256 threads (8 warps, warp tile 32x16).
// mode 0: Y = tanh(r);  mode 1: Y += tanh(r);  mode 2: Y = r
// ---------------------------------------------------------------------------
#define GXH 0
#define GXL 9216
#define GWH 18432
#define GWL 27648

__global__ __launch_bounds__(256)
void k_gemm_mma(const float* __restrict__ X, const float* __restrict__ X2,
                const float* __restrict__ W, const float* __restrict__ bias,
                float* __restrict__ Y, int Nv, int Kv, int mode) {
    __shared__ __align__(16) char smg[4 * 9216];
    const int tid  = threadIdx.x;
    const int wid  = tid >> 5;
    const int lane = tid & 31;
    const int mg   = wid & 1;    // 2 groups of 32 rows
    const int ng   = wid >> 1;   // 4 groups of 16 cols
    const int m0   = blockIdx.y * 64;
    const int n0   = blockIdx.x * 64;

    const uint32_t sbg = smem_u32(smg);
    const uint32_t aHiRow = sbg + GXH + (mg * 32 + (lane & 15)) * KSTR +
                            ((lane >> 4) << 4);
    const uint32_t aLoRow = aHiRow + (GXL - GXH);
    const uint32_t bHiRow = sbg + GWH + (ng * 16 + (lane & 7)) * KSTR +
                            (((lane >> 3) & 1) << 4);
    const uint32_t bLoRow = bHiRow + (GWL - GWH);

    float acc[2][2][4];
    #pragma unroll
    for (int a = 0; a < 2; a++)
        #pragma unroll
        for (int b = 0; b < 2; b++)
            #pragma unroll
            for (int e = 0; e < 4; e++) acc[a][b][e] = 0.f;

    // Loader role: 1024 float4 slots per matrix, 4 per thread
    const int nchunks = Kv >> 6;
    float4 xv[4], wv[4];
    #pragma unroll
    for (int j = 0; j < 4; j++) {
        int lin = j * 256 + tid;
        int row = lin >> 4, c4 = lin & 15;
        xv[j] = *(const float4*)&X[(size_t)(m0 + row) * Kv + c4 * 4];
        if (X2) {
            float4 t = *(const float4*)&X2[(size_t)(m0 + row) * Kv + c4 * 4];
            xv[j].x += t.x; xv[j].y += t.y; xv[j].z += t.z; xv[j].w += t.w;
        }
        wv[j] = *(const float4*)&W[(size_t)(n0 + row) * Kv + c4 * 4];
    }

    for (int c = 0; c < nchunks; c++) {
        __syncthreads();

        #pragma unroll
        for (int j = 0; j < 4; j++) {
            int lin = j * 256 + tid;
            int row = lin >> 4, c4 = lin & 15;
            uint2 h, l;
            h.x = split2(xv[j].x, xv[j].y, l.x);
            h.y = split2(xv[j].z, xv[j].w, l.y);
            *(uint2*)(smg + GXH + row * KSTR + c4 * 8) = h;
            *(uint2*)(smg + GXL + row * KSTR + c4 * 8) = l;
            h.x = split2(wv[j].x, wv[j].y, l.x);
            h.y = split2(wv[j].z, wv[j].w, l.y);
            *(uint2*)(smg + GWH + row * KSTR + c4 * 8) = h;
            *(uint2*)(smg + GWL + row * KSTR + c4 * 8) = l;
        }
        if (c + 1 < nchunks) {
            int k0 = (c + 1) * 64;
            #pragma unroll
            for (int j = 0; j < 4; j++) {
                int lin = j * 256 + tid;
                int row = lin >> 4, c4 = lin & 15;
                xv[j] = *(const float4*)&X[(size_t)(m0 + row) * Kv + k0 + c4 * 4];
                if (X2) {
                    float4 t = *(const float4*)&X2[(size_t)(m0 + row) * Kv + k0 + c4 * 4];
                    xv[j].x += t.x; xv[j].y += t.y; xv[j].z += t.z; xv[j].w += t.w;
                }
                wv[j] = *(const float4*)&W[(size_t)(n0 + row) * Kv + k0 + c4 * 4];
            }
        }
        __syncthreads();

        #pragma unroll
        for (int s = 0; s < 4; s++) {
            uint32_t bh[2][2], bl[2][2];
            #pragma unroll
            for (int nt = 0; nt < 2; nt++) {
                ldsm2(bh[nt], bHiRow + nt * 8 * KSTR + s * 32);
                ldsm2(bl[nt], bLoRow + nt * 8 * KSTR + s * 32);
            }
            #pragma unroll
            for (int mt = 0; mt < 2; mt++) {
                uint32_t af[4];
                ldsm4(af, aHiRow + mt * 16 * KSTR + s * 32);
                #pragma unroll
                for (int nt = 0; nt < 2; nt++) mma_bf16(acc[mt][nt], af, bh[nt]);
                #pragma unroll
                for (int nt = 0; nt < 2; nt++) mma_bf16(acc[mt][nt], af, bl[nt]);
                ldsm4(af, aLoRow + mt * 16 * KSTR + s * 32);
                #pragma unroll
                for (int nt = 0; nt < 2; nt++) mma_bf16(acc[mt][nt], af, bh[nt]);
            }
        }
    }

    // Epilogue
    const int g = lane >> 2;
    const int i = lane & 3;
    #pragma unroll
    for (int mt = 0; mt < 2; mt++) {
        #pragma unroll
        for (int nt = 0; nt < 2; nt++) {
            const float* d = acc[mt][nt];
            int n = n0 + ng * 16 + nt * 8 + 2 * i;
            float bia0 = bias[n], bia1 = bias[n + 1];
            #pragma unroll
            for (int e = 0; e < 4; e++) {
                int m  = m0 + mg * 32 + mt * 16 + g + (e >> 1) * 8;
                int nn = n + (e & 1);
                float v = d[e] + ((e & 1) ? bia1 : bia0);
                if (mode != 2) v = tanhf(v);
                size_t o = (size_t)m * Nv + nn;
                if (mode == 1) Y[o] += v;
                else           Y[o] = v;
            }
        }
    }
}

// ---------------------------------------------------------------------------
// Launch
// ---------------------------------------------------------------------------
extern "C" void kernel_launch(void* const* d_in, const int* in_sizes, int n_in,
                              void* d_out, int out_size) {
    const float* codes = (const float*)d_in[0];
    const float* cb    = (const float*)d_in[1];
    const float* w_in  = (const float*)d_in[2];
    const float* b_in  = (const float*)d_in[3];
    const float* w_h1  = (const float*)d_in[4];
    const float* b_h1  = (const float*)d_in[5];
    const float* w_s2  = (const float*)d_in[6];
    const float* b_s2  = (const float*)d_in[7];
    const float* w_s3  = (const float*)d_in[8];
    const float* b_s3  = (const float*)d_in[9];
    const float* w_h2  = (const float*)d_in[10];
    const float* b_h2  = (const float*)d_in[11];
    const float* w_s1o = (const float*)d_in[12];
    const float* b_s1o = (const float*)d_in[13];
    const float* w_s2o = (const float*)d_in[14];
    const float* b_s2o = (const float*)d_in[15];
    const float* w_h3  = (const float*)d_in[16];
    const float* b_h3  = (const float*)d_in[17];
    const float* w_mu  = (const float*)d_in[18];
    const float* b_mu  = (const float*)d_in[19];
    const float* w_s   = (const float*)d_in[20];
    const float* b_s   = (const float*)d_in[21];
    float* out = (float*)d_out;  // [mu (512*256), logstd (512*256)]

    float *p_prev, *p_i, *p_h1, *p_s2, *p_s3, *p_h2, *p_acc;
    cudaGetSymbolAddress((void**)&p_prev, g_prev);
    cudaGetSymbolAddress((void**)&p_i,    g_i);
    cudaGetSymbolAddress((void**)&p_h1,   g_h1);
    cudaGetSymbolAddress((void**)&p_s2,   g_s2);
    cudaGetSymbolAddress((void**)&p_s3,   g_s3);
    cudaGetSymbolAddress((void**)&p_h2,   g_h2);
    cudaGetSymbolAddress((void**)&p_acc,  g_acc);

    cudaFuncSetAttribute(k_nn_mma,
                         cudaFuncAttributeMaxDynamicSharedMemorySize, SM_NN);

    // Stage 1: exact-quality nearest neighbor via bf16x3 mma.sync
    k_prep_codes<<<BDIM, CDIM>>>(codes);
    k_init_best<<<1, 512>>>();
    k_nn_mma<<<NSLICE * 4, 512, SM_NN>>>(cb);
    k_gather<<<BDIM, CDIM>>>(cb);

    // Stage 2: MLP on tensor cores
    dim3 gH(HDIM / 64, BDIM / 64);   // (16, 8)
    dim3 gC(CDIM / 64, BDIM / 64);   // (4, 8)
    k_gemm_mma<<<gH, 256>>>(p_prev, nullptr, w_in,  b_in,  p_i,   HDIM, CDIM, 0);
    k_gemm_mma<<<gH, 256>>>(p_i,    nullptr, w_h1,  b_h1,  p_h1,  HDIM, HDIM, 0);
    k_gemm_mma<<<gH, 256>>>(p_h1,   nullptr, w_s2,  b_s2,  p_s2,  HDIM, HDIM, 0);
    k_gemm_mma<<<gH, 256>>>(p_h1,   nullptr, w_s3,  b_s3,  p_s3,  HDIM, HDIM, 0);
    k_gemm_mma<<<gH, 256>>>(p_h1,   p_s2,    w_h2,  b_h2,  p_h2,  HDIM, HDIM, 0);
    k_gemm_mma<<<gH, 256>>>(p_h1,   nullptr, w_s1o, b_s1o, p_acc, HDIM, HDIM, 0);
    k_gemm_mma<<<gH, 256>>>(p_h2,   nullptr, w_s2o, b_s2o, p_acc, HDIM, HDIM, 1);
    k_gemm_mma<<<gH, 256>>>(p_h2,   p_s3,    w_h3,  b_h3,  p_acc, HDIM, HDIM, 1);
    k_gemm_mma<<<gC, 256>>>(p_acc,  nullptr, w_mu,  b_mu,  out,               CDIM, HDIM, 2);
    k_gemm_mma<<<gC, 256>>>(p_acc,  nullptr, w_s,   b_s,   out + BDIM * CDIM, CDIM, HDIM, 2);
}